// round 4
// baseline (speedup 1.0000x reference)
#include <cuda_runtime.h>
#include <math.h>

#define HH 48
#define WW 160
#define PIX 7680            // HH*WW
#define NPAD 8192
#define NTILE 30            // 10 x 3 tiles of 16x16

// ---------------- scratch (device globals; no allocation) ----------------
__device__ float g_hw1[16*128*9];   // packed head conv1 weights
__device__ float g_hb1[16];         // packed head conv1 bias
__device__ float g_h1raw[16*PIX];   // head conv1 partial sums (atomic)
__device__ float g_h1act[16*PIX];   // gelu(head conv1)
__device__ float g_feat1[128*PIX];  // fl1 output
__device__ float g_gsfeat[64*PIX];  // fl2 output (gaussian features, [c][p])
__device__ float g_u[PIX], g_v[PIX], g_Ac[PIX], g_Bc[PIX], g_Cc[PIX], g_op[PIX];
__device__ float g_rx[PIX], g_ry[PIX];
__device__ unsigned g_zkey[PIX];
__device__ unsigned g_order[PIX];
__device__ float g_us[PIX], g_vs[PIX], g_As[PIX], g_Bs[PIX], g_Cs[PIX], g_os[PIX];
__device__ float g_rxs[PIX], g_rys[PIX];
__device__ float g_featS[PIX*64];   // sorted features [n][64]
__device__ float g_lev[64*PIX];     // rasterized level [c][p]
__device__ int   g_tlist[NTILE*PIX];
__device__ int   g_tcnt[NTILE];

// ---------------- helpers ----------------
template<int A>
__device__ __forceinline__ float actf(float v){
    if (A == 1) { // ELU
        return v > 0.f ? v : expm1f(v);
    }
    if (A == 2) { // GELU (tanh approx, jax default)
        float v3 = v*v*v;
        return 0.5f*v*(1.f + tanhf(0.7978845608028654f*(v + 0.044715f*v3)));
    }
    return v;
}

__device__ __forceinline__ unsigned smem_u32(const void* p){
    return (unsigned)__cvta_generic_to_shared(p);
}
#define CPA4(d,s)  asm volatile("cp.async.ca.shared.global [%0],[%1],4;\n"::"r"(d),"l"(s))
#define CPA16(d,s) asm volatile("cp.async.cg.shared.global [%0],[%1],16;\n"::"r"(d),"l"(s))
#define CPC  asm volatile("cp.async.commit_group;\n")
#define CPW0 asm volatile("cp.async.wait_group 0;\n")

// ---------------- generic tiled 3x3 conv, double-buffered cp.async ----------------
// Tile: 32 (x) by 8 (y) pixels, 16 output channels per block.
// 128 threads: tco=tid>>6 (2 groups of 8 co), ty=(tid&63)>>3, tx=tid&7 (4 px each).
// PADM: 0=reflect, 1=edge.  ACT: 0=raw atomic partial, 1=ELU, 2=GELU.
// CSPLIT: split input channels across gridDim.z (atomicAdd partials).
template<int CIN, int PADM, int ACT, int CSPLIT>
__global__ __launch_bounds__(128)
void conv3x3_t(const float* __restrict__ in, const float* __restrict__ wgt,
               const float* __restrict__ bias, float* __restrict__ out)
{
    __shared__ float s_in[2][8*10*37];   // 8 cin x 10 rows x 37 (pad) cols
    __shared__ float s_w[2][16*72];      // 16 co x 8 cin x 9 taps

    const int tid = threadIdx.x;
    const int tco = tid >> 6;
    const int r   = tid & 63;
    const int ty  = r >> 3;
    const int tx  = r & 7;
    const int x0  = blockIdx.x * 32;
    const int y0  = blockIdx.y * 8;
    const int ncog = gridDim.z / CSPLIT;
    const int cog  = blockIdx.z % ncog;
    const int csp  = blockIdx.z / ncog;
    const int cin0 = csp * (CIN / CSPLIT);
    const int coB  = cog * 16;

    float acc[8][4];
    #pragma unroll
    for (int a = 0; a < 8; a++)
        #pragma unroll
        for (int b = 0; b < 4; b++) acc[a][b] = 0.f;

    const int CHUNKS = CIN / CSPLIT / 8;

    auto load_chunk = [&](int ch, int buf) {
        const int cb = cin0 + ch * 8;
        unsigned sin_b = smem_u32(&s_in[buf][0]);
        unsigned sw_b  = smem_u32(&s_w[buf][0]);
        // input tile: 8 cin x 10 rows x 34 cols (4B cp.async, computed indices)
        for (int e = tid; e < 2720; e += 128) {
            int ci = e / 340; int rem = e - ci * 340;
            int rr = rem / 34; int cc = rem - rr * 34;
            int yi = y0 - 1 + rr, xi = x0 - 1 + cc;
            if (PADM == 0) { // reflect
                yi = yi < 0 ? -yi : (yi >= HH ? 2*HH-2-yi : yi);
                xi = xi < 0 ? -xi : (xi >= WW ? 2*WW-2-xi : xi);
            } else {         // edge
                yi = yi < 0 ? 0 : (yi >= HH ? HH-1 : yi);
                xi = xi < 0 ? 0 : (xi >= WW ? WW-1 : xi);
            }
            CPA4(sin_b + (unsigned)(ci*370 + rr*37 + cc)*4u,
                 in + (size_t)(cb + ci)*PIX + yi*WW + xi);
        }
        // weights: 16 co x 72 floats contiguous per co -> float4 cp.async
        for (int e = tid; e < 288; e += 128) {
            int co = e / 18, rem = e - co * 18;
            const float* src = wgt + (size_t)(coB + co)*(CIN*9) + cb*9 + rem*4;
            CPA16(sw_b + (unsigned)e*16u, src);
        }
        CPC;
    };

    load_chunk(0, 0);
    CPW0; __syncthreads();

    for (int ch = 0; ch < CHUNKS; ch++) {
        const int cur = ch & 1;
        if (ch + 1 < CHUNKS) load_chunk(ch + 1, cur ^ 1);

        #pragma unroll
        for (int ci = 0; ci < 8; ci++) {
            float xv[3][6];
            #pragma unroll
            for (int kh = 0; kh < 3; kh++)
                #pragma unroll
                for (int c2 = 0; c2 < 6; c2++)
                    xv[kh][c2] = s_in[cur][ci*370 + (ty+kh)*37 + tx*4 + c2];
            #pragma unroll
            for (int kh = 0; kh < 3; kh++)
                #pragma unroll
                for (int kw = 0; kw < 3; kw++) {
                    #pragma unroll
                    for (int co = 0; co < 8; co++) {
                        float wv = s_w[cur][(tco*8+co)*72 + ci*9 + kh*3 + kw];
                        #pragma unroll
                        for (int px = 0; px < 4; px++)
                            acc[co][px] = fmaf(xv[kh][kw+px], wv, acc[co][px]);
                    }
                }
        }

        if (ch + 1 < CHUNKS) CPW0;
        __syncthreads();
    }

    const int x = x0 + tx*4, y = y0 + ty;
    #pragma unroll
    for (int co = 0; co < 8; co++) {
        const int cg = coB + tco*8 + co;
        float* op = out + (size_t)cg*PIX + y*WW + x;
        if (CSPLIT > 1) {
            #pragma unroll
            for (int px = 0; px < 4; px++) atomicAdd(op + px, acc[co][px]);
        } else {
            const float b = bias[cg];
            float4 vv;
            vv.x = actf<ACT>(acc[co][0] + b);
            vv.y = actf<ACT>(acc[co][1] + b);
            vv.z = actf<ACT>(acc[co][2] + b);
            vv.w = actf<ACT>(acc[co][3] + b);
            *reinterpret_cast<float4*>(op) = vv;
        }
    }
}

// ---------------- prep: pack head conv1 weights + zero partial buffer ----------------
__global__ void prep_kernel(const float* __restrict__ rw1, const float* __restrict__ sw1,
                            const float* __restrict__ ow1, const float* __restrict__ rb1,
                            const float* __restrict__ sb1, const float* __restrict__ ob1)
{
    int i = blockIdx.x * 256 + threadIdx.x;
    if (i < 16*1152) {
        int co = i / 1152, rem = i - co*1152;
        float v;
        if (co < 8)       v = rw1[co*1152 + rem];
        else if (co < 14) v = sw1[(co-8)*1152 + rem];
        else              v = ow1[(co-14)*1152 + rem];
        g_hw1[i] = v;
    }
    if (i < 16) {
        float b;
        if (i < 8)       b = rb1[i];
        else if (i < 14) b = sb1[i-8];
        else             b = ob1[i-14];
        g_hb1[i] = b;
    }
    if (i < 16*PIX) g_h1raw[i] = 0.f;
}

__global__ void h1_epilogue_kernel()
{
    int i = blockIdx.x * 256 + threadIdx.x;
    if (i < 16*PIX) {
        int c = i / PIX;
        float v = g_h1raw[i] + g_hb1[c];
        float v3 = v*v*v;
        g_h1act[i] = 0.5f*v*(1.f + tanhf(0.7978845608028654f*(v + 0.044715f*v3)));
    }
}

// ---------------- head conv2 + gaussian precompute ----------------
__global__ void heads2_kernel(const float* __restrict__ disp,
                              const float* __restrict__ invK, const float* __restrict__ Kmat,
                              const float* __restrict__ rw2, const float* __restrict__ rb2,
                              const float* __restrict__ sw2, const float* __restrict__ sb2,
                              const float* __restrict__ ow2, const float* __restrict__ ob2)
{
    int p = blockIdx.x * 256 + threadIdx.x;
    if (p >= PIX) return;
    int yy = p / WW, xx = p - yy*WW;

    int nb[9];
    #pragma unroll
    for (int kh = 0; kh < 3; kh++) {
        int yi = yy - 1 + kh; yi = yi < 0 ? 0 : (yi >= HH ? HH-1 : yi);  // edge pad
        #pragma unroll
        for (int kw = 0; kw < 3; kw++) {
            int xi = xx - 1 + kw; xi = xi < 0 ? 0 : (xi >= WW ? WW-1 : xi);
            nb[kh*3+kw] = yi*WW + xi;
        }
    }

    // rot head conv2: 8 -> 4
    float q[4] = { rb2[0], rb2[1], rb2[2], rb2[3] };
    for (int ci = 0; ci < 8; ci++) {
        #pragma unroll
        for (int t = 0; t < 9; t++) {
            float a = g_h1act[ci*PIX + nb[t]];
            #pragma unroll
            for (int k = 0; k < 4; k++) q[k] = fmaf(a, rw2[k*72 + ci*9 + t], q[k]);
        }
    }
    float nrm = sqrtf(q[0]*q[0] + q[1]*q[1] + q[2]*q[2] + q[3]*q[3]);
    nrm = fmaxf(nrm, 1e-12f);
    float inr = 1.f / nrm;
    float qw = q[0]*inr, qx = q[1]*inr, qy = q[2]*inr, qz = q[3]*inr;

    // scale head conv2: 6 -> 3, abs
    float s3[3] = { sb2[0], sb2[1], sb2[2] };
    for (int ci = 0; ci < 6; ci++) {
        #pragma unroll
        for (int t = 0; t < 9; t++) {
            float a = g_h1act[(8+ci)*PIX + nb[t]];
            #pragma unroll
            for (int k = 0; k < 3; k++) s3[k] = fmaf(a, sw2[k*54 + ci*9 + t], s3[k]);
        }
    }
    float s0 = fabsf(s3[0]), s1 = fabsf(s3[1]), s2 = fabsf(s3[2]);

    // opacity head conv2: 2 -> 1, sigmoid
    float ov = ob2[0];
    for (int ci = 0; ci < 2; ci++) {
        #pragma unroll
        for (int t = 0; t < 9; t++)
            ov = fmaf(g_h1act[(14+ci)*PIX + nb[t]], ow2[ci*9 + t], ov);
    }
    float opa = 1.f / (1.f + expf(-ov));

    // depth & position
    float dsp = disp[p];
    float scaled = (1.f/100.f) + (1.f/0.1f - 1.f/100.f) * dsp;
    float d = 1.f / scaled;
    d = fminf(fmaxf(d, 0.1f), 100.f);
    float fxp = (float)xx, fyp = (float)yy;
    float X = (invK[0]*fxp + invK[1]*fyp + invK[2])  * d;
    float Y = (invK[4]*fxp + invK[5]*fyp + invK[6])  * d;
    float Z = (invK[8]*fxp + invK[9]*fyp + invK[10]) * d;

    float fx = Kmat[0], fy = Kmat[5], cx = Kmat[2], cy = Kmat[6];

    // quat -> rot, column-scaled
    float r00 = 1.f - 2.f*(qy*qy + qz*qz), r01 = 2.f*(qx*qy - qw*qz), r02 = 2.f*(qx*qz + qw*qy);
    float r10 = 2.f*(qx*qy + qw*qz), r11 = 1.f - 2.f*(qx*qx + qz*qz), r12 = 2.f*(qy*qz - qw*qx);
    float r20 = 2.f*(qx*qz - qw*qy), r21 = 2.f*(qy*qz + qw*qx), r22 = 1.f - 2.f*(qx*qx + qy*qy);
    float m00 = r00*s0, m01 = r01*s1, m02 = r02*s2;
    float m10 = r10*s0, m11 = r11*s1, m12 = r12*s2;
    float m20 = r20*s0, m21 = r21*s1, m22 = r22*s2;
    float S00 = m00*m00 + m01*m01 + m02*m02;
    float S01 = m00*m10 + m01*m11 + m02*m12;
    float S02 = m00*m20 + m01*m21 + m02*m22;
    float S11 = m10*m10 + m11*m11 + m12*m12;
    float S12 = m10*m20 + m11*m21 + m12*m22;
    float S22 = m20*m20 + m21*m21 + m22*m22;

    float iz = 1.f / Z;
    float j00 = fx*iz,  j02 = -fx*X*iz*iz;
    float j11 = fy*iz,  j12 = -fy*Y*iz*iz;
    float t00 = j00*S00 + j02*S02;
    float t01 = j00*S01 + j02*S12;
    float t02 = j00*S02 + j02*S22;
    float cov00 = t00*j00 + t02*j02;
    float cov01 = t01*j11 + t02*j12;
    float t11 = j11*S11 + j12*S12;
    float t12 = j11*S12 + j12*S22;
    float cov11 = t11*j11 + t12*j12;

    float a = cov00 + 0.3f, b = cov01, c = cov11 + 0.3f;
    float det = a*c - b*b;
    float idet = 1.f / det;

    g_u[p]  = fx*X*iz + cx;
    g_v[p]  = fy*Y*iz + cy;
    g_Ac[p] = c * idet;
    g_Bc[p] = -b * idet;
    g_Cc[p] = a * idet;
    g_op[p] = opa;
    // exact ellipse extents of {power >= -20}:  max|dx| = sqrt(40*(H^-1)_00) = sqrt(40*a)
    g_rx[p] = sqrtf(40.f*a);
    g_ry[p] = sqrtf(40.f*c);
    g_zkey[p] = __float_as_uint(Z);   // Z > 0 for this camera
}

// ---------------- bitonic sort (single block, 8192 slots, 48KB smem) ----------------
__global__ __launch_bounds__(1024) void sort_kernel()
{
    __shared__ unsigned skey[NPAD];
    __shared__ unsigned short sidx[NPAD];
    const int tid = threadIdx.x;
    for (int i = tid; i < NPAD; i += 1024) {
        skey[i] = (i < PIX) ? g_zkey[i] : 0xFFFFFFFFu;
        sidx[i] = (unsigned short)i;
    }
    __syncthreads();
    for (int k = 2; k <= NPAD; k <<= 1) {
        for (int j = k >> 1; j > 0; j >>= 1) {
            for (int i = tid; i < NPAD; i += 1024) {
                int ixj = i ^ j;
                if (ixj > i) {
                    bool up = ((i & k) == 0);
                    unsigned a = skey[i], b = skey[ixj];
                    unsigned short ia = sidx[i], ib = sidx[ixj];
                    bool gt = (a > b) || (a == b && ia > ib);
                    if (gt == up) {
                        skey[i] = b; skey[ixj] = a;
                        sidx[i] = ib; sidx[ixj] = ia;
                    }
                }
            }
            __syncthreads();
        }
    }
    for (int i = tid; i < PIX; i += 1024) g_order[i] = sidx[i];
}

// ---------------- gather sorted SoA ----------------
__global__ void gather_kernel()
{
    int idx = blockIdx.x * 256 + threadIdx.x;
    if (idx >= PIX*64) return;
    int n = idx >> 6, c = idx & 63;
    unsigned p = g_order[n];
    g_featS[idx] = g_gsfeat[c*PIX + p];
    if (c == 0) g_us[n] = g_u[p];
    else if (c == 1) g_vs[n] = g_v[p];
    else if (c == 2) g_As[n] = g_Ac[p];
    else if (c == 3) g_Bs[n] = g_Bc[p];
    else if (c == 4) g_Cs[n] = g_Cc[p];
    else if (c == 5) g_os[n] = g_op[p];
    else if (c == 6) g_rxs[n] = g_rx[p];
    else if (c == 7) g_rys[n] = g_ry[p];
}

// ---------------- tile binning: warp per 16x16 tile, order-preserving compact ----------------
__global__ __launch_bounds__(32) void bin_kernel()
{
    const int tile = blockIdx.x;
    const int lane = threadIdx.x;
    const float x0 = (float)((tile % 10) * 16);
    const float y0 = (float)((tile / 10) * 16);
    const float x1 = x0 + 15.f, y1 = y0 + 15.f;
    int* list = g_tlist + tile * PIX;
    int cnt = 0;
    for (int base = 0; base < PIX; base += 32) {
        int n = base + lane;
        float u = g_us[n], v = g_vs[n], rx = g_rxs[n], ry = g_rys[n];
        bool hit = (u - rx <= x1) && (u + rx >= x0) && (v - ry <= y1) && (v + ry >= y0);
        unsigned m = __ballot_sync(0xffffffffu, hit);
        if (hit) list[cnt + __popc(m & ((1u << lane) - 1u))] = n;
        cnt += __popc(m);
    }
    if (lane == 0) g_tcnt[tile] = cnt;
}

// ---------------- rasterize: thread per pixel, per-tile lists, exact sequential T ----------------
__global__ __launch_bounds__(256) void raster_kernel()
{
    __shared__ int   sn[64];
    __shared__ float su[64], sv[64], sA[64], sB[64], sC[64], so[64];
    __shared__ float sf[64*32];

    const int tile = blockIdx.x;
    const int half = blockIdx.y;       // channels [half*32, half*32+32)
    const int tid  = threadIdx.x;
    const int px = (tile % 10) * 16 + (tid & 15);
    const int py = (tile / 10) * 16 + (tid >> 4);
    const float gx = (float)px, gy = (float)py;

    const int cnt = g_tcnt[tile];
    const int* list = g_tlist + tile * PIX;

    float acc[32];
    #pragma unroll
    for (int c = 0; c < 32; c++) acc[c] = 0.f;
    float T = 1.f;
    bool done = false;

    for (int base = 0; base < cnt; base += 64) {
        const int m = min(64, cnt - base);
        __syncthreads();
        if (tid < m) {
            int n = list[base + tid];
            sn[tid] = n;
            su[tid] = g_us[n]; sv[tid] = g_vs[n];
            sA[tid] = g_As[n]; sB[tid] = g_Bs[n];
            sC[tid] = g_Cs[n]; so[tid] = g_os[n];
        }
        __syncthreads();
        for (int e = tid; e < m * 32; e += 256) {
            int g = e >> 5, c = e & 31;
            sf[e] = g_featS[(size_t)sn[g]*64 + half*32 + c];
        }
        __syncthreads();

        if (done) continue;
        for (int g = 0; g < m; g++) {
            float dx = gx - su[g], dy = gy - sv[g];
            float pw = -0.5f*(sA[g]*dx*dx + sC[g]*dy*dy) - sB[g]*dx*dy;
            if (pw <= 0.f && pw > -20.f) {
                float alpha = fminf(so[g]*__expf(pw), 0.99f);
                float w = alpha * T;
                T -= w;                      // T *= (1 - alpha)
                if (w > 1e-9f) {
                    const float4* fp = reinterpret_cast<const float4*>(sf + g*32);
                    #pragma unroll
                    for (int c4 = 0; c4 < 8; c4++) {
                        float4 f = fp[c4];
                        acc[c4*4+0] = fmaf(w, f.x, acc[c4*4+0]);
                        acc[c4*4+1] = fmaf(w, f.y, acc[c4*4+1]);
                        acc[c4*4+2] = fmaf(w, f.z, acc[c4*4+2]);
                        acc[c4*4+3] = fmaf(w, f.w, acc[c4*4+3]);
                    }
                }
                if (T < 1e-7f) { done = true; break; }
            }
        }
    }

    const int p = py * WW + px;
    #pragma unroll
    for (int c = 0; c < 32; c++)
        g_lev[(size_t)(half*32 + c)*PIX + p] = acc[c];
}

// ---------------- launch ----------------
extern "C" void kernel_launch(void* const* d_in, const int* in_sizes, int n_in,
                              void* d_out, int out_size)
{
    const float* init_feature = (const float*)d_in[0];
    const float* disp   = (const float*)d_in[1];
    const float* invK   = (const float*)d_in[2];
    const float* Kmat   = (const float*)d_in[3];
    const float* rot_w1 = (const float*)d_in[4];
    const float* rot_b1 = (const float*)d_in[5];
    const float* rot_w2 = (const float*)d_in[6];
    const float* rot_b2 = (const float*)d_in[7];
    const float* scl_w1 = (const float*)d_in[8];
    const float* scl_b1 = (const float*)d_in[9];
    const float* scl_w2 = (const float*)d_in[10];
    const float* scl_b2 = (const float*)d_in[11];
    const float* opa_w1 = (const float*)d_in[12];
    const float* opa_b1 = (const float*)d_in[13];
    const float* opa_w2 = (const float*)d_in[14];
    const float* opa_b2 = (const float*)d_in[15];
    const float* fl_w1  = (const float*)d_in[16];
    const float* fl_b1  = (const float*)d_in[17];
    const float* fl_w2  = (const float*)d_in[18];
    const float* fl_b2  = (const float*)d_in[19];
    const float* fr_w   = (const float*)d_in[20];
    const float* fr_b   = (const float*)d_in[21];
    float* out = (float*)d_out;

    float *p_hw1, *p_h1raw, *p_feat1, *p_gsfeat, *p_lev;
    cudaGetSymbolAddress((void**)&p_hw1,    g_hw1);
    cudaGetSymbolAddress((void**)&p_h1raw,  g_h1raw);
    cudaGetSymbolAddress((void**)&p_feat1,  g_feat1);
    cudaGetSymbolAddress((void**)&p_gsfeat, g_gsfeat);
    cudaGetSymbolAddress((void**)&p_lev,    g_lev);

    // 1. pack head conv1 weights + zero partials
    prep_kernel<<<480, 256>>>(rot_w1, scl_w1, opa_w1, rot_b1, scl_b1, opa_b1);

    // 2. head conv1: 128->16, edge pad, cin-split 4 (atomic partials), then gelu
    conv3x3_t<128, 1, 0, 4><<<dim3(5, 6, 4), 128>>>(init_feature, p_hw1, nullptr, p_h1raw);
    h1_epilogue_kernel<<<480, 256>>>();

    // 3. feature convs: fl1 128->128 reflect ELU, fl2 128->64 reflect ELU
    conv3x3_t<128, 0, 1, 1><<<dim3(5, 6, 8), 128>>>(init_feature, fl_w1, fl_b1, p_feat1);
    conv3x3_t<128, 0, 1, 1><<<dim3(5, 6, 4), 128>>>(p_feat1, fl_w2, fl_b2, p_gsfeat);

    // 4. head conv2 + per-gaussian precompute
    heads2_kernel<<<30, 256>>>(disp, invK, Kmat, rot_w2, rot_b2, scl_w2, scl_b2, opa_w2, opa_b2);

    // 5. depth sort + gather sorted SoA
    sort_kernel<<<1, 1024>>>();
    gather_kernel<<<1920, 256>>>();

    // 6. tile binning + rasterize
    bin_kernel<<<NTILE, 32>>>();
    raster_kernel<<<dim3(NTILE, 2), 256>>>();

    // 7. final conv: 64->128 reflect ELU -> out
    conv3x3_t<64, 0, 1, 1><<<dim3(5, 6, 8), 128>>>(p_lev, fr_w, fr_b, out);
}

// round 6
// speedup vs baseline: 2.1104x; 2.1104x over previous
#include <cuda_runtime.h>
#include <math.h>

#define HH 48
#define WW 160
#define PIX 7680            // HH*WW
#define NPAD 8192
#define NTILE 30            // 10 x 3 tiles of 16x16

// ---------------- scratch (device globals; no allocation) ----------------
__device__ float g_hw1[16*128*9];   // packed head conv1 weights
__device__ float g_hb1[16];         // packed head conv1 bias
__device__ float g_h1raw[16*PIX];   // head conv1 partial sums (atomic)
__device__ float g_h1act[16*PIX];   // gelu(head conv1)
__device__ float g_feat1[128*PIX];  // fl1 output
__device__ float g_gsfeat[64*PIX];  // fl2 output (gaussian features, [c][p])
__device__ float g_u[PIX], g_v[PIX], g_Ac[PIX], g_Bc[PIX], g_Cc[PIX], g_op[PIX];
__device__ float g_rx[PIX], g_ry[PIX];
__device__ unsigned g_zkey[PIX];
__device__ unsigned g_order[PIX];
__device__ float g_us[PIX], g_vs[PIX], g_As[PIX], g_Bs[PIX], g_Cs[PIX], g_os[PIX];
__device__ float g_rxs[PIX], g_rys[PIX];
__device__ float g_featS[PIX*64];   // sorted features [n][64]
__device__ float g_lev[64*PIX];     // rasterized level [c][p]
__device__ int   g_tlist[NTILE*PIX];  // per tile: 8 segments of 960
__device__ int   g_scnt[NTILE*8];

// ---------------- helpers ----------------
template<int A>
__device__ __forceinline__ float actf(float v){
    if (A == 1) { // ELU
        return v > 0.f ? v : expm1f(v);
    }
    if (A == 2) { // GELU (tanh approx, jax default)
        float v3 = v*v*v;
        return 0.5f*v*(1.f + tanhf(0.7978845608028654f*(v + 0.044715f*v3)));
    }
    return v;
}

// ---------------- generic tiled 3x3 conv (sync smem loads, hoisted addressing) ----
// Tile: 32 (x) by 8 (y) pixels, 16 output channels per block.
// 128 threads: tco=tid>>6 (2 groups of 8 co), ty=(tid&63)>>3, tx=tid&7 (4 px each).
// PADM: 0=reflect, 1=edge.  ACT: 0=raw atomic partial, 1=ELU, 2=GELU.
// CSPLIT: split input channels across gridDim.z (atomicAdd partials).
template<int CIN, int PADM, int ACT, int CSPLIT>
__global__ __launch_bounds__(128)
void conv3x3_t(const float* __restrict__ in, const float* __restrict__ wgt,
               const float* __restrict__ bias, float* __restrict__ out)
{
    __shared__ float s_in[8*10*37];   // 8 cin x 10 rows x 37 (pad) cols
    __shared__ float s_w[16*72];      // 16 co x 8 cin x 9 taps

    const int tid = threadIdx.x;
    const int tco = tid >> 6;
    const int r   = tid & 63;
    const int ty  = r >> 3;
    const int tx  = r & 7;
    const int x0  = blockIdx.x * 32;
    const int y0  = blockIdx.y * 8;
    const int ncog = gridDim.z / CSPLIT;
    const int cog  = blockIdx.z % ncog;
    const int csp  = blockIdx.z / ncog;
    const int cin0 = csp * (CIN / CSPLIT);
    const int coB  = cog * 16;

    // ---- precompute per-thread load offsets (once; reused every chunk) ----
    // input plane: 340 elems (10 rows x 34 cols); threads cover it in <=3 slots
    int soffp[3], doffp[3];
    #pragma unroll
    for (int j = 0; j < 3; j++) {
        int e = tid + 128*j;
        if (e < 340) {
            int rr = e / 34, cc = e - rr * 34;
            int yi = y0 - 1 + rr, xi = x0 - 1 + cc;
            if (PADM == 0) { // reflect
                yi = yi < 0 ? -yi : (yi >= HH ? 2*HH-2-yi : yi);
                xi = xi < 0 ? -xi : (xi >= WW ? 2*WW-2-xi : xi);
            } else {         // edge
                yi = yi < 0 ? 0 : (yi >= HH ? HH-1 : yi);
                xi = xi < 0 ? 0 : (xi >= WW ? WW-1 : xi);
            }
            soffp[j] = yi*WW + xi;
            doffp[j] = rr*37 + cc;
        }
    }
    // weights: 288 float4 slots; threads cover in <=3 slots
    int woffp[3];
    #pragma unroll
    for (int j = 0; j < 3; j++) {
        int e = tid + 128*j;
        if (e < 288) {
            int co = e / 18, rem = e - co * 18;
            woffp[j] = (coB + co)*(CIN*9) + rem*4;
        }
    }

    float acc[8][4];
    #pragma unroll
    for (int a = 0; a < 8; a++)
        #pragma unroll
        for (int b = 0; b < 4; b++) acc[a][b] = 0.f;

    const int CHUNKS = CIN / CSPLIT / 8;
    for (int ch = 0; ch < CHUNKS; ch++) {
        const int cb = cin0 + ch * 8;
        __syncthreads();
        // input tile: 8 planes, hoisted offsets, fully unrolled (24 indep LDG)
        const float* inb = in + (size_t)cb * PIX;
        #pragma unroll
        for (int ci = 0; ci < 8; ci++) {
            #pragma unroll
            for (int j = 0; j < 3; j++) {
                int e = tid + 128*j;
                if (e < 340)
                    s_in[ci*370 + doffp[j]] = inb[(size_t)ci*PIX + soffp[j]];
            }
        }
        // weights: float4 loads
        const float* wb = wgt + cb*9;
        #pragma unroll
        for (int j = 0; j < 3; j++) {
            int e = tid + 128*j;
            if (e < 288)
                *reinterpret_cast<float4*>(&s_w[e*4]) =
                    *reinterpret_cast<const float4*>(&wb[woffp[j]]);
        }
        __syncthreads();

        #pragma unroll
        for (int ci = 0; ci < 8; ci++) {
            float xv[3][6];
            #pragma unroll
            for (int kh = 0; kh < 3; kh++)
                #pragma unroll
                for (int c2 = 0; c2 < 6; c2++)
                    xv[kh][c2] = s_in[ci*370 + (ty+kh)*37 + tx*4 + c2];
            #pragma unroll
            for (int kh = 0; kh < 3; kh++)
                #pragma unroll
                for (int kw = 0; kw < 3; kw++) {
                    #pragma unroll
                    for (int co = 0; co < 8; co++) {
                        float wv = s_w[(tco*8+co)*72 + ci*9 + kh*3 + kw];
                        #pragma unroll
                        for (int px = 0; px < 4; px++)
                            acc[co][px] = fmaf(xv[kh][kw+px], wv, acc[co][px]);
                    }
                }
        }
    }

    const int x = x0 + tx*4, y = y0 + ty;
    #pragma unroll
    for (int co = 0; co < 8; co++) {
        const int cg = coB + tco*8 + co;
        float* op = out + (size_t)cg*PIX + y*WW + x;
        if (CSPLIT > 1) {
            #pragma unroll
            for (int px = 0; px < 4; px++) atomicAdd(op + px, acc[co][px]);
        } else {
            const float b = bias[cg];
            float4 vv;
            vv.x = actf<ACT>(acc[co][0] + b);
            vv.y = actf<ACT>(acc[co][1] + b);
            vv.z = actf<ACT>(acc[co][2] + b);
            vv.w = actf<ACT>(acc[co][3] + b);
            *reinterpret_cast<float4*>(op) = vv;
        }
    }
}

// ---------------- prep: pack head conv1 weights + zero partial buffer ----------------
__global__ void prep_kernel(const float* __restrict__ rw1, const float* __restrict__ sw1,
                            const float* __restrict__ ow1, const float* __restrict__ rb1,
                            const float* __restrict__ sb1, const float* __restrict__ ob1)
{
    int i = blockIdx.x * 256 + threadIdx.x;
    if (i < 16*1152) {
        int co = i / 1152, rem = i - co*1152;
        float v;
        if (co < 8)       v = rw1[co*1152 + rem];
        else if (co < 14) v = sw1[(co-8)*1152 + rem];
        else              v = ow1[(co-14)*1152 + rem];
        g_hw1[i] = v;
    }
    if (i < 16) {
        float b;
        if (i < 8)       b = rb1[i];
        else if (i < 14) b = sb1[i-8];
        else             b = ob1[i-14];
        g_hb1[i] = b;
    }
    if (i < 16*PIX) g_h1raw[i] = 0.f;
}

__global__ void h1_epilogue_kernel()
{
    int i = blockIdx.x * 256 + threadIdx.x;
    if (i < 16*PIX) {
        int c = i / PIX;
        float v = g_h1raw[i] + g_hb1[c];
        float v3 = v*v*v;
        g_h1act[i] = 0.5f*v*(1.f + tanhf(0.7978845608028654f*(v + 0.044715f*v3)));
    }
}

// ---------------- head conv2 + gaussian precompute ----------------
__global__ void heads2_kernel(const float* __restrict__ disp,
                              const float* __restrict__ invK, const float* __restrict__ Kmat,
                              const float* __restrict__ rw2, const float* __restrict__ rb2,
                              const float* __restrict__ sw2, const float* __restrict__ sb2,
                              const float* __restrict__ ow2, const float* __restrict__ ob2)
{
    int p = blockIdx.x * 256 + threadIdx.x;
    if (p >= PIX) return;
    int yy = p / WW, xx = p - yy*WW;

    int nb[9];
    #pragma unroll
    for (int kh = 0; kh < 3; kh++) {
        int yi = yy - 1 + kh; yi = yi < 0 ? 0 : (yi >= HH ? HH-1 : yi);  // edge pad
        #pragma unroll
        for (int kw = 0; kw < 3; kw++) {
            int xi = xx - 1 + kw; xi = xi < 0 ? 0 : (xi >= WW ? WW-1 : xi);
            nb[kh*3+kw] = yi*WW + xi;
        }
    }

    // rot head conv2: 8 -> 4
    float q[4] = { rb2[0], rb2[1], rb2[2], rb2[3] };
    for (int ci = 0; ci < 8; ci++) {
        #pragma unroll
        for (int t = 0; t < 9; t++) {
            float a = g_h1act[ci*PIX + nb[t]];
            #pragma unroll
            for (int k = 0; k < 4; k++) q[k] = fmaf(a, rw2[k*72 + ci*9 + t], q[k]);
        }
    }
    float nrm = sqrtf(q[0]*q[0] + q[1]*q[1] + q[2]*q[2] + q[3]*q[3]);
    nrm = fmaxf(nrm, 1e-12f);
    float inr = 1.f / nrm;
    float qw = q[0]*inr, qx = q[1]*inr, qy = q[2]*inr, qz = q[3]*inr;

    // scale head conv2: 6 -> 3, abs
    float s3[3] = { sb2[0], sb2[1], sb2[2] };
    for (int ci = 0; ci < 6; ci++) {
        #pragma unroll
        for (int t = 0; t < 9; t++) {
            float a = g_h1act[(8+ci)*PIX + nb[t]];
            #pragma unroll
            for (int k = 0; k < 3; k++) s3[k] = fmaf(a, sw2[k*54 + ci*9 + t], s3[k]);
        }
    }
    float s0 = fabsf(s3[0]), s1 = fabsf(s3[1]), s2 = fabsf(s3[2]);

    // opacity head conv2: 2 -> 1, sigmoid
    float ov = ob2[0];
    for (int ci = 0; ci < 2; ci++) {
        #pragma unroll
        for (int t = 0; t < 9; t++)
            ov = fmaf(g_h1act[(14+ci)*PIX + nb[t]], ow2[ci*9 + t], ov);
    }
    float opa = 1.f / (1.f + expf(-ov));

    // depth & position
    float dsp = disp[p];
    float scaled = (1.f/100.f) + (1.f/0.1f - 1.f/100.f) * dsp;
    float d = 1.f / scaled;
    d = fminf(fmaxf(d, 0.1f), 100.f);
    float fxp = (float)xx, fyp = (float)yy;
    float X = (invK[0]*fxp + invK[1]*fyp + invK[2])  * d;
    float Y = (invK[4]*fxp + invK[5]*fyp + invK[6])  * d;
    float Z = (invK[8]*fxp + invK[9]*fyp + invK[10]) * d;

    float fx = Kmat[0], fy = Kmat[5], cx = Kmat[2], cy = Kmat[6];

    // quat -> rot, column-scaled
    float r00 = 1.f - 2.f*(qy*qy + qz*qz), r01 = 2.f*(qx*qy - qw*qz), r02 = 2.f*(qx*qz + qw*qy);
    float r10 = 2.f*(qx*qy + qw*qz), r11 = 1.f - 2.f*(qx*qx + qz*qz), r12 = 2.f*(qy*qz - qw*qx);
    float r20 = 2.f*(qx*qz - qw*qy), r21 = 2.f*(qy*qz + qw*qx), r22 = 1.f - 2.f*(qx*qx + qy*qy);
    float m00 = r00*s0, m01 = r01*s1, m02 = r02*s2;
    float m10 = r10*s0, m11 = r11*s1, m12 = r12*s2;
    float m20 = r20*s0, m21 = r21*s1, m22 = r22*s2;
    float S00 = m00*m00 + m01*m01 + m02*m02;
    float S01 = m00*m10 + m01*m11 + m02*m12;
    float S02 = m00*m20 + m01*m21 + m02*m22;
    float S11 = m10*m10 + m11*m11 + m12*m12;
    float S12 = m10*m20 + m11*m21 + m12*m22;
    float S22 = m20*m20 + m21*m21 + m22*m22;

    float iz = 1.f / Z;
    float j00 = fx*iz,  j02 = -fx*X*iz*iz;
    float j11 = fy*iz,  j12 = -fy*Y*iz*iz;
    float t00 = j00*S00 + j02*S02;
    float t01 = j00*S01 + j02*S12;
    float t02 = j00*S02 + j02*S22;
    float cov00 = t00*j00 + t02*j02;
    float cov01 = t01*j11 + t02*j12;
    float t11 = j11*S11 + j12*S12;
    float t12 = j11*S12 + j12*S22;
    float cov11 = t11*j11 + t12*j12;

    float a = cov00 + 0.3f, b = cov01, c = cov11 + 0.3f;
    float det = a*c - b*b;
    float idet = 1.f / det;

    g_u[p]  = fx*X*iz + cx;
    g_v[p]  = fy*Y*iz + cy;
    g_Ac[p] = c * idet;
    g_Bc[p] = -b * idet;
    g_Cc[p] = a * idet;
    g_op[p] = opa;
    // exact ellipse extents of {power >= -20}:  max|dx| = sqrt(40*(H^-1)_00) = sqrt(40*a)
    g_rx[p] = sqrtf(40.f*a);
    g_ry[p] = sqrtf(40.f*c);
    g_zkey[p] = __float_as_uint(Z);   // Z > 0 for this camera
}

// ---------------- bitonic sort (single block, 8192 slots, 48KB smem) ----------------
__global__ __launch_bounds__(1024) void sort_kernel()
{
    __shared__ unsigned skey[NPAD];
    __shared__ unsigned short sidx[NPAD];
    const int tid = threadIdx.x;
    for (int i = tid; i < NPAD; i += 1024) {
        skey[i] = (i < PIX) ? g_zkey[i] : 0xFFFFFFFFu;
        sidx[i] = (unsigned short)i;
    }
    __syncthreads();
    for (int k = 2; k <= NPAD; k <<= 1) {
        for (int j = k >> 1; j > 0; j >>= 1) {
            for (int i = tid; i < NPAD; i += 1024) {
                int ixj = i ^ j;
                if (ixj > i) {
                    bool up = ((i & k) == 0);
                    unsigned a = skey[i], b = skey[ixj];
                    unsigned short ia = sidx[i], ib = sidx[ixj];
                    bool gt = (a > b) || (a == b && ia > ib);
                    if (gt == up) {
                        skey[i] = b; skey[ixj] = a;
                        sidx[i] = ib; sidx[ixj] = ia;
                    }
                }
            }
            __syncthreads();
        }
    }
    for (int i = tid; i < PIX; i += 1024) g_order[i] = sidx[i];
}

// ---------------- gather sorted SoA ----------------
__global__ void gather_kernel()
{
    int idx = blockIdx.x * 256 + threadIdx.x;
    if (idx >= PIX*64) return;
    int n = idx >> 6, c = idx & 63;
    unsigned p = g_order[n];
    g_featS[idx] = g_gsfeat[c*PIX + p];
    if (c == 0) g_us[n] = g_u[p];
    else if (c == 1) g_vs[n] = g_v[p];
    else if (c == 2) g_As[n] = g_Ac[p];
    else if (c == 3) g_Bs[n] = g_Bc[p];
    else if (c == 4) g_Cs[n] = g_Cc[p];
    else if (c == 5) g_os[n] = g_op[p];
    else if (c == 6) g_rxs[n] = g_rx[p];
    else if (c == 7) g_rys[n] = g_ry[p];
}

// -------- tile binning: 8 warps per tile, depth-ordered segments of 960 --------
__global__ __launch_bounds__(256) void bin_kernel()
{
    const int tile = blockIdx.x;
    const int lane = threadIdx.x & 31;
    const int w    = threadIdx.x >> 5;
    const float x0 = (float)((tile % 10) * 16);
    const float y0 = (float)((tile / 10) * 16);
    const float x1 = x0 + 15.f, y1 = y0 + 15.f;
    int* list = g_tlist + tile * PIX + w * 960;
    int cnt = 0;
    for (int b = 0; b < 960; b += 32) {
        int n = w*960 + b + lane;
        float u = g_us[n], v = g_vs[n], rx = g_rxs[n], ry = g_rys[n];
        bool hit = (u - rx <= x1) && (u + rx >= x0) && (v - ry <= y1) && (v + ry >= y0);
        unsigned m = __ballot_sync(0xffffffffu, hit);
        if (hit) list[cnt + __popc(m & ((1u << lane) - 1u))] = n;
        cnt += __popc(m);
    }
    if (lane == 0) g_scnt[tile*8 + w] = cnt;
}

// ---- rasterize: thread per pixel, per-tile segment lists, 16 channels/block ----
__global__ __launch_bounds__(256) void raster_kernel()
{
    __shared__ int   sn[64];
    __shared__ float su[64], sv[64], sA[64], sB[64], sC[64], so[64];
    __shared__ float sf[64*16];

    const int tile = blockIdx.x;
    const int q    = blockIdx.y;       // channel quarter [q*16, q*16+16)
    const int tid  = threadIdx.x;
    const int px = (tile % 10) * 16 + (tid & 15);
    const int py = (tile / 10) * 16 + (tid >> 4);
    const float gx = (float)px, gy = (float)py;

    float acc[16];
    #pragma unroll
    for (int c = 0; c < 16; c++) acc[c] = 0.f;
    float T = 1.f;
    bool done = false;
    bool alldone = false;

    for (int seg = 0; seg < 8 && !alldone; seg++) {
        const int cnt = g_scnt[tile*8 + seg];
        const int* list = g_tlist + tile * PIX + seg * 960;

        for (int base = 0; base < cnt; base += 64) {
            const int m = min(64, cnt - base);
            __syncthreads();
            if (tid < m) {
                int n = list[base + tid];
                sn[tid] = n;
                su[tid] = g_us[n]; sv[tid] = g_vs[n];
                sA[tid] = g_As[n]; sB[tid] = g_Bs[n];
                sC[tid] = g_Cs[n]; so[tid] = g_os[n];
            }
            __syncthreads();
            for (int e = tid; e < m * 16; e += 256) {
                int g = e >> 4, c = e & 15;
                sf[e] = g_featS[(size_t)sn[g]*64 + q*16 + c];
            }
            __syncthreads();

            if (!done) {
                for (int g = 0; g < m; g++) {
                    float dx = gx - su[g], dy = gy - sv[g];
                    float pw = -0.5f*(sA[g]*dx*dx + sC[g]*dy*dy) - sB[g]*dx*dy;
                    if (pw <= 0.f && pw > -20.f) {
                        float alpha = fminf(so[g]*__expf(pw), 0.99f);
                        float wv = alpha * T;
                        T -= wv;                      // T *= (1 - alpha)
                        if (wv > 1e-9f) {
                            const float4* fp = reinterpret_cast<const float4*>(sf + g*16);
                            #pragma unroll
                            for (int c4 = 0; c4 < 4; c4++) {
                                float4 f = fp[c4];
                                acc[c4*4+0] = fmaf(wv, f.x, acc[c4*4+0]);
                                acc[c4*4+1] = fmaf(wv, f.y, acc[c4*4+1]);
                                acc[c4*4+2] = fmaf(wv, f.z, acc[c4*4+2]);
                                acc[c4*4+3] = fmaf(wv, f.w, acc[c4*4+3]);
                            }
                        }
                        if (T < 1e-7f) { done = true; }
                    }
                }
            }
            if (__syncthreads_and(done)) { alldone = true; break; }
        }
    }

    const int p = py * WW + px;
    #pragma unroll
    for (int c = 0; c < 16; c++)
        g_lev[(size_t)(q*16 + c)*PIX + p] = acc[c];
}

// ---------------- launch ----------------
extern "C" void kernel_launch(void* const* d_in, const int* in_sizes, int n_in,
                              void* d_out, int out_size)
{
    const float* init_feature = (const float*)d_in[0];
    const float* disp   = (const float*)d_in[1];
    const float* invK   = (const float*)d_in[2];
    const float* Kmat   = (const float*)d_in[3];
    const float* rot_w1 = (const float*)d_in[4];
    const float* rot_b1 = (const float*)d_in[5];
    const float* rot_w2 = (const float*)d_in[6];
    const float* rot_b2 = (const float*)d_in[7];
    const float* scl_w1 = (const float*)d_in[8];
    const float* scl_b1 = (const float*)d_in[9];
    const float* scl_w2 = (const float*)d_in[10];
    const float* scl_b2 = (const float*)d_in[11];
    const float* opa_w1 = (const float*)d_in[12];
    const float* opa_b1 = (const float*)d_in[13];
    const float* opa_w2 = (const float*)d_in[14];
    const float* opa_b2 = (const float*)d_in[15];
    const float* fl_w1  = (const float*)d_in[16];
    const float* fl_b1  = (const float*)d_in[17];
    const float* fl_w2  = (const float*)d_in[18];
    const float* fl_b2  = (const float*)d_in[19];
    const float* fr_w   = (const float*)d_in[20];
    const float* fr_b   = (const float*)d_in[21];
    float* out = (float*)d_out;

    float *p_hw1, *p_h1raw, *p_feat1, *p_gsfeat, *p_lev;
    cudaGetSymbolAddress((void**)&p_hw1,    g_hw1);
    cudaGetSymbolAddress((void**)&p_h1raw,  g_h1raw);
    cudaGetSymbolAddress((void**)&p_feat1,  g_feat1);
    cudaGetSymbolAddress((void**)&p_gsfeat, g_gsfeat);
    cudaGetSymbolAddress((void**)&p_lev,    g_lev);

    // 1. pack head conv1 weights + zero partials
    prep_kernel<<<480, 256>>>(rot_w1, scl_w1, opa_w1, rot_b1, scl_b1, opa_b1);

    // 2. head conv1: 128->16, edge pad, cin-split 4 (atomic partials), then gelu
    conv3x3_t<128, 1, 0, 4><<<dim3(5, 6, 4), 128>>>(init_feature, p_hw1, nullptr, p_h1raw);
    h1_epilogue_kernel<<<480, 256>>>();

    // 3. feature convs: fl1 128->128 reflect ELU, fl2 128->64 reflect ELU
    conv3x3_t<128, 0, 1, 1><<<dim3(5, 6, 8), 128>>>(init_feature, fl_w1, fl_b1, p_feat1);
    conv3x3_t<128, 0, 1, 1><<<dim3(5, 6, 4), 128>>>(p_feat1, fl_w2, fl_b2, p_gsfeat);

    // 4. head conv2 + per-gaussian precompute
    heads2_kernel<<<30, 256>>>(disp, invK, Kmat, rot_w2, rot_b2, scl_w2, scl_b2, opa_w2, opa_b2);

    // 5. depth sort + gather sorted SoA
    sort_kernel<<<1, 1024>>>();
    gather_kernel<<<1920, 256>>>();

    // 6. tile binning (8 depth-ordered segments per tile) + rasterize (4 ch-quarters)
    bin_kernel<<<NTILE, 256>>>();
    raster_kernel<<<dim3(NTILE, 4), 256>>>();

    // 7. final conv: 64->128 reflect ELU -> out
    conv3x3_t<64, 0, 1, 1><<<dim3(5, 6, 8), 128>>>(p_lev, fr_w, fr_b, out);
}

// round 7
// speedup vs baseline: 2.9831x; 1.4135x over previous
#include <cuda_runtime.h>
#include <math.h>

#define HH 48
#define WW 160
#define PIX 7680            // HH*WW
#define NPAD 8192
#define NTILE 30            // 10 x 3 tiles of 16x16

// ---------------- scratch (device globals; no allocation) ----------------
__device__ float g_hw1[16*128*9];   // packed head conv1 weights
__device__ float g_hb1[16];         // packed head conv1 bias
__device__ float g_h1raw[16*PIX];   // head conv1 partial sums (atomic)
__device__ float g_h1act[16*PIX];   // gelu(head conv1)
__device__ float g_feat1[128*PIX];  // fl1 output [c][p]
__device__ float g_featT[PIX*64];   // fl2 output TRANSPOSED [p][64]
__device__ float4 g_parA[PIX];      // (u, v, A, B)
__device__ float4 g_parB[PIX];      // (C, opa, rx, ry)
__device__ unsigned g_zkey[PIX];
__device__ unsigned g_order[PIX];
__device__ float g_us[PIX], g_vs[PIX], g_As[PIX], g_Bs[PIX], g_Cs[PIX], g_os[PIX];
__device__ float g_rxs[PIX], g_rys[PIX];
__device__ int   g_porig[PIX];      // sorted -> original pixel id
__device__ float g_lev[64*PIX];     // rasterized level [c][p]
__device__ int   g_tlist[NTILE*PIX];  // per tile: 8 segments of 960
__device__ int   g_scnt[NTILE*8];

// ---------------- helpers ----------------
template<int A>
__device__ __forceinline__ float actf(float v){
    if (A == 1) { // ELU
        return v > 0.f ? v : expm1f(v);
    }
    if (A == 2) { // GELU (tanh approx, jax default)
        float v3 = v*v*v;
        return 0.5f*v*(1.f + tanhf(0.7978845608028654f*(v + 0.044715f*v3)));
    }
    return v;
}

// ---------------- generic tiled 3x3 conv (sync smem loads, hoisted addressing) ----
// Tile: 32 (x) by 8 (y) pixels, 16 output channels per block.
// 128 threads: tco=tid>>6 (2 groups of 8 co), ty=(tid&63)>>3, tx=tid&7 (4 px each).
// PADM: 0=reflect, 1=edge.  ACT: 0=raw atomic partial, 1=ELU, 2=GELU.
// CSPLIT: split input channels across gridDim.z (atomicAdd partials).
// OUTT: 1 = write transposed [p][64] layout (requires 64 total out channels).
template<int CIN, int PADM, int ACT, int CSPLIT, int OUTT>
__global__ __launch_bounds__(128)
void conv3x3_t(const float* __restrict__ in, const float* __restrict__ wgt,
               const float* __restrict__ bias, float* __restrict__ out)
{
    __shared__ float s_in[8*10*37];   // 8 cin x 10 rows x 37 (pad) cols
    __shared__ float s_w[16*72];      // 16 co x 8 cin x 9 taps

    const int tid = threadIdx.x;
    const int tco = tid >> 6;
    const int r   = tid & 63;
    const int ty  = r >> 3;
    const int tx  = r & 7;
    const int x0  = blockIdx.x * 32;
    const int y0  = blockIdx.y * 8;
    const int ncog = gridDim.z / CSPLIT;
    const int cog  = blockIdx.z % ncog;
    const int csp  = blockIdx.z / ncog;
    const int cin0 = csp * (CIN / CSPLIT);
    const int coB  = cog * 16;

    // ---- precompute per-thread load offsets (once; reused every chunk) ----
    int soffp[3], doffp[3];
    #pragma unroll
    for (int j = 0; j < 3; j++) {
        int e = tid + 128*j;
        if (e < 340) {
            int rr = e / 34, cc = e - rr * 34;
            int yi = y0 - 1 + rr, xi = x0 - 1 + cc;
            if (PADM == 0) { // reflect
                yi = yi < 0 ? -yi : (yi >= HH ? 2*HH-2-yi : yi);
                xi = xi < 0 ? -xi : (xi >= WW ? 2*WW-2-xi : xi);
            } else {         // edge
                yi = yi < 0 ? 0 : (yi >= HH ? HH-1 : yi);
                xi = xi < 0 ? 0 : (xi >= WW ? WW-1 : xi);
            }
            soffp[j] = yi*WW + xi;
            doffp[j] = rr*37 + cc;
        }
    }
    int woffp[3];
    #pragma unroll
    for (int j = 0; j < 3; j++) {
        int e = tid + 128*j;
        if (e < 288) {
            int co = e / 18, rem = e - co * 18;
            woffp[j] = (coB + co)*(CIN*9) + rem*4;
        }
    }

    float acc[8][4];
    #pragma unroll
    for (int a = 0; a < 8; a++)
        #pragma unroll
        for (int b = 0; b < 4; b++) acc[a][b] = 0.f;

    const int CHUNKS = CIN / CSPLIT / 8;
    for (int ch = 0; ch < CHUNKS; ch++) {
        const int cb = cin0 + ch * 8;
        __syncthreads();
        const float* inb = in + (size_t)cb * PIX;
        #pragma unroll
        for (int ci = 0; ci < 8; ci++) {
            #pragma unroll
            for (int j = 0; j < 3; j++) {
                int e = tid + 128*j;
                if (e < 340)
                    s_in[ci*370 + doffp[j]] = inb[(size_t)ci*PIX + soffp[j]];
            }
        }
        const float* wb = wgt + cb*9;
        #pragma unroll
        for (int j = 0; j < 3; j++) {
            int e = tid + 128*j;
            if (e < 288)
                *reinterpret_cast<float4*>(&s_w[e*4]) =
                    *reinterpret_cast<const float4*>(&wb[woffp[j]]);
        }
        __syncthreads();

        #pragma unroll
        for (int ci = 0; ci < 8; ci++) {
            float xv[3][6];
            #pragma unroll
            for (int kh = 0; kh < 3; kh++)
                #pragma unroll
                for (int c2 = 0; c2 < 6; c2++)
                    xv[kh][c2] = s_in[ci*370 + (ty+kh)*37 + tx*4 + c2];
            #pragma unroll
            for (int kh = 0; kh < 3; kh++)
                #pragma unroll
                for (int kw = 0; kw < 3; kw++) {
                    #pragma unroll
                    for (int co = 0; co < 8; co++) {
                        float wv = s_w[(tco*8+co)*72 + ci*9 + kh*3 + kw];
                        #pragma unroll
                        for (int px = 0; px < 4; px++)
                            acc[co][px] = fmaf(xv[kh][kw+px], wv, acc[co][px]);
                    }
                }
        }
    }

    const int x = x0 + tx*4, y = y0 + ty;
    if (CSPLIT > 1) {
        #pragma unroll
        for (int co = 0; co < 8; co++) {
            const int cg = coB + tco*8 + co;
            float* op = out + (size_t)cg*PIX + y*WW + x;
            #pragma unroll
            for (int px = 0; px < 4; px++) atomicAdd(op + px, acc[co][px]);
        }
    } else if (OUTT) {
        float bs[8];
        #pragma unroll
        for (int co = 0; co < 8; co++) bs[co] = bias[coB + tco*8 + co];
        #pragma unroll
        for (int px = 0; px < 4; px++) {
            int p = y*WW + x + px;
            float* op = out + (size_t)p*64 + coB + tco*8;
            float4 v0, v1;
            v0.x = actf<ACT>(acc[0][px] + bs[0]);
            v0.y = actf<ACT>(acc[1][px] + bs[1]);
            v0.z = actf<ACT>(acc[2][px] + bs[2]);
            v0.w = actf<ACT>(acc[3][px] + bs[3]);
            v1.x = actf<ACT>(acc[4][px] + bs[4]);
            v1.y = actf<ACT>(acc[5][px] + bs[5]);
            v1.z = actf<ACT>(acc[6][px] + bs[6]);
            v1.w = actf<ACT>(acc[7][px] + bs[7]);
            reinterpret_cast<float4*>(op)[0] = v0;
            reinterpret_cast<float4*>(op)[1] = v1;
        }
    } else {
        #pragma unroll
        for (int co = 0; co < 8; co++) {
            const int cg = coB + tco*8 + co;
            float* op = out + (size_t)cg*PIX + y*WW + x;
            const float b = bias[cg];
            float4 vv;
            vv.x = actf<ACT>(acc[co][0] + b);
            vv.y = actf<ACT>(acc[co][1] + b);
            vv.z = actf<ACT>(acc[co][2] + b);
            vv.w = actf<ACT>(acc[co][3] + b);
            *reinterpret_cast<float4*>(op) = vv;
        }
    }
}

// ---------------- prep: pack head conv1 weights + zero partial buffer ----------------
__global__ void prep_kernel(const float* __restrict__ rw1, const float* __restrict__ sw1,
                            const float* __restrict__ ow1, const float* __restrict__ rb1,
                            const float* __restrict__ sb1, const float* __restrict__ ob1)
{
    int i = blockIdx.x * 256 + threadIdx.x;
    if (i < 16*1152) {
        int co = i / 1152, rem = i - co*1152;
        float v;
        if (co < 8)       v = rw1[co*1152 + rem];
        else if (co < 14) v = sw1[(co-8)*1152 + rem];
        else              v = ow1[(co-14)*1152 + rem];
        g_hw1[i] = v;
    }
    if (i < 16) {
        float b;
        if (i < 8)       b = rb1[i];
        else if (i < 14) b = sb1[i-8];
        else             b = ob1[i-14];
        g_hb1[i] = b;
    }
    if (i < 16*PIX) g_h1raw[i] = 0.f;
}

__global__ void h1_epilogue_kernel()
{
    int i = blockIdx.x * 256 + threadIdx.x;
    if (i < 16*PIX) {
        int c = i / PIX;
        float v = g_h1raw[i] + g_hb1[c];
        float v3 = v*v*v;
        g_h1act[i] = 0.5f*v*(1.f + tanhf(0.7978845608028654f*(v + 0.044715f*v3)));
    }
}

// ---------------- head conv2 + gaussian precompute ----------------
__global__ void heads2_kernel(const float* __restrict__ disp,
                              const float* __restrict__ invK, const float* __restrict__ Kmat,
                              const float* __restrict__ rw2, const float* __restrict__ rb2,
                              const float* __restrict__ sw2, const float* __restrict__ sb2,
                              const float* __restrict__ ow2, const float* __restrict__ ob2)
{
    int p = blockIdx.x * 256 + threadIdx.x;
    if (p >= PIX) return;
    int yy = p / WW, xx = p - yy*WW;

    int nb[9];
    #pragma unroll
    for (int kh = 0; kh < 3; kh++) {
        int yi = yy - 1 + kh; yi = yi < 0 ? 0 : (yi >= HH ? HH-1 : yi);  // edge pad
        #pragma unroll
        for (int kw = 0; kw < 3; kw++) {
            int xi = xx - 1 + kw; xi = xi < 0 ? 0 : (xi >= WW ? WW-1 : xi);
            nb[kh*3+kw] = yi*WW + xi;
        }
    }

    // rot head conv2: 8 -> 4
    float q[4] = { rb2[0], rb2[1], rb2[2], rb2[3] };
    for (int ci = 0; ci < 8; ci++) {
        #pragma unroll
        for (int t = 0; t < 9; t++) {
            float a = g_h1act[ci*PIX + nb[t]];
            #pragma unroll
            for (int k = 0; k < 4; k++) q[k] = fmaf(a, rw2[k*72 + ci*9 + t], q[k]);
        }
    }
    float nrm = sqrtf(q[0]*q[0] + q[1]*q[1] + q[2]*q[2] + q[3]*q[3]);
    nrm = fmaxf(nrm, 1e-12f);
    float inr = 1.f / nrm;
    float qw = q[0]*inr, qx = q[1]*inr, qy = q[2]*inr, qz = q[3]*inr;

    // scale head conv2: 6 -> 3, abs
    float s3[3] = { sb2[0], sb2[1], sb2[2] };
    for (int ci = 0; ci < 6; ci++) {
        #pragma unroll
        for (int t = 0; t < 9; t++) {
            float a = g_h1act[(8+ci)*PIX + nb[t]];
            #pragma unroll
            for (int k = 0; k < 3; k++) s3[k] = fmaf(a, sw2[k*54 + ci*9 + t], s3[k]);
        }
    }
    float s0 = fabsf(s3[0]), s1 = fabsf(s3[1]), s2 = fabsf(s3[2]);

    // opacity head conv2: 2 -> 1, sigmoid
    float ov = ob2[0];
    for (int ci = 0; ci < 2; ci++) {
        #pragma unroll
        for (int t = 0; t < 9; t++)
            ov = fmaf(g_h1act[(14+ci)*PIX + nb[t]], ow2[ci*9 + t], ov);
    }
    float opa = 1.f / (1.f + expf(-ov));

    // depth & position
    float dsp = disp[p];
    float scaled = (1.f/100.f) + (1.f/0.1f - 1.f/100.f) * dsp;
    float d = 1.f / scaled;
    d = fminf(fmaxf(d, 0.1f), 100.f);
    float fxp = (float)xx, fyp = (float)yy;
    float X = (invK[0]*fxp + invK[1]*fyp + invK[2])  * d;
    float Y = (invK[4]*fxp + invK[5]*fyp + invK[6])  * d;
    float Z = (invK[8]*fxp + invK[9]*fyp + invK[10]) * d;

    float fx = Kmat[0], fy = Kmat[5], cx = Kmat[2], cy = Kmat[6];

    // quat -> rot, column-scaled
    float r00 = 1.f - 2.f*(qy*qy + qz*qz), r01 = 2.f*(qx*qy - qw*qz), r02 = 2.f*(qx*qz + qw*qy);
    float r10 = 2.f*(qx*qy + qw*qz), r11 = 1.f - 2.f*(qx*qx + qz*qz), r12 = 2.f*(qy*qz - qw*qx);
    float r20 = 2.f*(qx*qz - qw*qy), r21 = 2.f*(qy*qz + qw*qx), r22 = 1.f - 2.f*(qx*qx + qy*qy);
    float m00 = r00*s0, m01 = r01*s1, m02 = r02*s2;
    float m10 = r10*s0, m11 = r11*s1, m12 = r12*s2;
    float m20 = r20*s0, m21 = r21*s1, m22 = r22*s2;
    float S00 = m00*m00 + m01*m01 + m02*m02;
    float S01 = m00*m10 + m01*m11 + m02*m12;
    float S02 = m00*m20 + m01*m21 + m02*m22;
    float S11 = m10*m10 + m11*m11 + m12*m12;
    float S12 = m10*m20 + m11*m21 + m12*m22;
    float S22 = m20*m20 + m21*m21 + m22*m22;

    float iz = 1.f / Z;
    float j00 = fx*iz,  j02 = -fx*X*iz*iz;
    float j11 = fy*iz,  j12 = -fy*Y*iz*iz;
    float t00 = j00*S00 + j02*S02;
    float t01 = j00*S01 + j02*S12;
    float t02 = j00*S02 + j02*S22;
    float cov00 = t00*j00 + t02*j02;
    float cov01 = t01*j11 + t02*j12;
    float t11 = j11*S11 + j12*S12;
    float t12 = j11*S12 + j12*S22;
    float cov11 = t11*j11 + t12*j12;

    float a = cov00 + 0.3f, b = cov01, c = cov11 + 0.3f;
    float det = a*c - b*b;
    float idet = 1.f / det;

    float A = c * idet, Bq = -b * idet, C = a * idet;
    g_parA[p] = make_float4(fx*X*iz + cx, fy*Y*iz + cy, A, Bq);
    // exact ellipse extents of {power >= -20}:  max|dx| = sqrt(40*(H^-1)_00) = sqrt(40*a)
    g_parB[p] = make_float4(C, opa, sqrtf(40.f*a), sqrtf(40.f*c));
    g_zkey[p] = __float_as_uint(Z);   // Z > 0 for this camera
}

// ---------------- bitonic sort (single block, 8192 slots, 48KB smem) ----------------
__global__ __launch_bounds__(1024) void sort_kernel()
{
    __shared__ unsigned skey[NPAD];
    __shared__ unsigned short sidx[NPAD];
    const int tid = threadIdx.x;
    for (int i = tid; i < NPAD; i += 1024) {
        skey[i] = (i < PIX) ? g_zkey[i] : 0xFFFFFFFFu;
        sidx[i] = (unsigned short)i;
    }
    __syncthreads();
    for (int k = 2; k <= NPAD; k <<= 1) {
        for (int j = k >> 1; j > 0; j >>= 1) {
            for (int i = tid; i < NPAD; i += 1024) {
                int ixj = i ^ j;
                if (ixj > i) {
                    bool up = ((i & k) == 0);
                    unsigned a = skey[i], b = skey[ixj];
                    unsigned short ia = sidx[i], ib = sidx[ixj];
                    bool gt = (a > b) || (a == b && ia > ib);
                    if (gt == up) {
                        skey[i] = b; skey[ixj] = a;
                        sidx[i] = ib; sidx[ixj] = ia;
                    }
                }
            }
            __syncthreads();
        }
    }
    for (int i = tid; i < PIX; i += 1024) g_order[i] = sidx[i];
}

// ---------------- gather params into sorted SoA (features stay in place) -------------
__global__ void gatherP_kernel()
{
    int n = blockIdx.x * 256 + threadIdx.x;
    if (n >= PIX) return;
    unsigned p = g_order[n];
    float4 a = g_parA[p], b = g_parB[p];
    g_us[n] = a.x;  g_vs[n] = a.y;  g_As[n] = a.z;  g_Bs[n] = a.w;
    g_Cs[n] = b.x;  g_os[n] = b.y;  g_rxs[n] = b.z; g_rys[n] = b.w;
    g_porig[n] = (int)p;
}

// -------- tile binning: 8 warps per tile, depth-ordered segments of 960 --------
__global__ __launch_bounds__(256) void bin_kernel()
{
    const int tile = blockIdx.x;
    const int lane = threadIdx.x & 31;
    const int w    = threadIdx.x >> 5;
    const float x0 = (float)((tile % 10) * 16);
    const float y0 = (float)((tile / 10) * 16);
    const float x1 = x0 + 15.f, y1 = y0 + 15.f;
    int* list = g_tlist + tile * PIX + w * 960;
    int cnt = 0;
    for (int b = 0; b < 960; b += 32) {
        int n = w*960 + b + lane;
        float u = g_us[n], v = g_vs[n], rx = g_rxs[n], ry = g_rys[n];
        bool hit = (u - rx <= x1) && (u + rx >= x0) && (v - ry <= y1) && (v + ry >= y0);
        unsigned m = __ballot_sync(0xffffffffu, hit);
        if (hit) list[cnt + __popc(m & ((1u << lane) - 1u))] = n;
        cnt += __popc(m);
    }
    if (lane == 0) g_scnt[tile*8 + w] = cnt;
}

// ---- rasterize: thread per pixel, per-tile segment lists, 16 channels/block ----
__global__ __launch_bounds__(256) void raster_kernel()
{
    __shared__ int   sp[64];
    __shared__ float su[64], sv[64], sA[64], sB[64], sC[64], so[64];
    __shared__ float sf[64*16];

    const int tile = blockIdx.x;
    const int q    = blockIdx.y;       // channel quarter [q*16, q*16+16)
    const int tid  = threadIdx.x;
    const int px = (tile % 10) * 16 + (tid & 15);
    const int py = (tile / 10) * 16 + (tid >> 4);
    const float gx = (float)px, gy = (float)py;

    float acc[16];
    #pragma unroll
    for (int c = 0; c < 16; c++) acc[c] = 0.f;
    float T = 1.f;
    bool done = false;
    bool alldone = false;

    for (int seg = 0; seg < 8 && !alldone; seg++) {
        const int cnt = g_scnt[tile*8 + seg];
        const int* list = g_tlist + tile * PIX + seg * 960;

        for (int base = 0; base < cnt; base += 64) {
            const int m = min(64, cnt - base);
            __syncthreads();
            if (tid < m) {
                int n = list[base + tid];
                sp[tid] = g_porig[n];
                su[tid] = g_us[n]; sv[tid] = g_vs[n];
                sA[tid] = g_As[n]; sB[tid] = g_Bs[n];
                sC[tid] = g_Cs[n]; so[tid] = g_os[n];
            }
            __syncthreads();
            for (int e = tid; e < m * 16; e += 256) {
                int g = e >> 4, c = e & 15;
                sf[e] = g_featT[(size_t)sp[g]*64 + q*16 + c];
            }
            __syncthreads();

            if (!done) {
                for (int g = 0; g < m; g++) {
                    float dx = gx - su[g], dy = gy - sv[g];
                    float pw = -0.5f*(sA[g]*dx*dx + sC[g]*dy*dy) - sB[g]*dx*dy;
                    if (pw <= 0.f && pw > -20.f) {
                        float alpha = fminf(so[g]*__expf(pw), 0.99f);
                        float wv = alpha * T;
                        T -= wv;                      // T *= (1 - alpha)
                        if (wv > 1e-9f) {
                            const float4* fp = reinterpret_cast<const float4*>(sf + g*16);
                            #pragma unroll
                            for (int c4 = 0; c4 < 4; c4++) {
                                float4 f = fp[c4];
                                acc[c4*4+0] = fmaf(wv, f.x, acc[c4*4+0]);
                                acc[c4*4+1] = fmaf(wv, f.y, acc[c4*4+1]);
                                acc[c4*4+2] = fmaf(wv, f.z, acc[c4*4+2]);
                                acc[c4*4+3] = fmaf(wv, f.w, acc[c4*4+3]);
                            }
                        }
                        if (T < 1e-7f) { done = true; }
                    }
                }
            }
            if (__syncthreads_and(done)) { alldone = true; break; }
        }
    }

    const int p = py * WW + px;
    #pragma unroll
    for (int c = 0; c < 16; c++)
        g_lev[(size_t)(q*16 + c)*PIX + p] = acc[c];
}

// ---------------- launch ----------------
extern "C" void kernel_launch(void* const* d_in, const int* in_sizes, int n_in,
                              void* d_out, int out_size)
{
    const float* init_feature = (const float*)d_in[0];
    const float* disp   = (const float*)d_in[1];
    const float* invK   = (const float*)d_in[2];
    const float* Kmat   = (const float*)d_in[3];
    const float* rot_w1 = (const float*)d_in[4];
    const float* rot_b1 = (const float*)d_in[5];
    const float* rot_w2 = (const float*)d_in[6];
    const float* rot_b2 = (const float*)d_in[7];
    const float* scl_w1 = (const float*)d_in[8];
    const float* scl_b1 = (const float*)d_in[9];
    const float* scl_w2 = (const float*)d_in[10];
    const float* scl_b2 = (const float*)d_in[11];
    const float* opa_w1 = (const float*)d_in[12];
    const float* opa_b1 = (const float*)d_in[13];
    const float* opa_w2 = (const float*)d_in[14];
    const float* opa_b2 = (const float*)d_in[15];
    const float* fl_w1  = (const float*)d_in[16];
    const float* fl_b1  = (const float*)d_in[17];
    const float* fl_w2  = (const float*)d_in[18];
    const float* fl_b2  = (const float*)d_in[19];
    const float* fr_w   = (const float*)d_in[20];
    const float* fr_b   = (const float*)d_in[21];
    float* out = (float*)d_out;

    float *p_hw1, *p_h1raw, *p_feat1, *p_featT, *p_lev;
    cudaGetSymbolAddress((void**)&p_hw1,    g_hw1);
    cudaGetSymbolAddress((void**)&p_h1raw,  g_h1raw);
    cudaGetSymbolAddress((void**)&p_feat1,  g_feat1);
    cudaGetSymbolAddress((void**)&p_featT,  g_featT);
    cudaGetSymbolAddress((void**)&p_lev,    g_lev);

    // lazily-created side stream + events (host-side only; created once,
    // reused; all captured work is identical every call)
    static cudaStream_t s1 = nullptr;
    static cudaEvent_t e0 = nullptr, e1 = nullptr;
    if (!s1) {
        cudaStreamCreateWithFlags(&s1, cudaStreamNonBlocking);
        cudaEventCreateWithFlags(&e0, cudaEventDisableTiming);
        cudaEventCreateWithFlags(&e1, cudaEventDisableTiming);
    }

    // fork: side chain (head path) runs concurrently with main conv chain
    cudaEventRecord(e0, 0);
    cudaStreamWaitEvent(s1, e0, 0);

    // ---- side chain (s1): head conv path -> sort -> param gather -> bin ----
    prep_kernel<<<480, 256, 0, s1>>>(rot_w1, scl_w1, opa_w1, rot_b1, scl_b1, opa_b1);
    conv3x3_t<128, 1, 0, 4, 0><<<dim3(5, 6, 4), 128, 0, s1>>>(init_feature, p_hw1, nullptr, p_h1raw);
    h1_epilogue_kernel<<<480, 256, 0, s1>>>();
    heads2_kernel<<<30, 256, 0, s1>>>(disp, invK, Kmat, rot_w2, rot_b2, scl_w2, scl_b2, opa_w2, opa_b2);
    sort_kernel<<<1, 1024, 0, s1>>>();
    gatherP_kernel<<<30, 256, 0, s1>>>();
    bin_kernel<<<NTILE, 256, 0, s1>>>();
    cudaEventRecord(e1, s1);

    // ---- main chain (default stream): feature convs ----
    conv3x3_t<128, 0, 1, 1, 0><<<dim3(5, 6, 8), 128>>>(init_feature, fl_w1, fl_b1, p_feat1);
    conv3x3_t<128, 0, 1, 1, 1><<<dim3(5, 6, 4), 128>>>(p_feat1, fl_w2, fl_b2, p_featT);

    // join, then rasterize + final conv
    cudaStreamWaitEvent(0, e1, 0);
    raster_kernel<<<dim3(NTILE, 4), 256>>>();
    conv3x3_t<64, 0, 1, 1, 0><<<dim3(5, 6, 8), 128>>>(p_lev, fr_w, fr_b, out);
}

// round 11
// speedup vs baseline: 3.3524x; 1.1238x over previous
#include <cuda_runtime.h>
#include <math.h>

#define HH 48
#define WW 160
#define PIX 7680            // HH*WW
#define NPAD 8192
#define NTILE 30            // 10 x 3 raster tiles of 16x16 (R7 geometry)
#define NT 1920             // winograd tiles: 24 x 80

// ---------------- scratch (device globals; no allocation) ----------------
__device__ float g_hw1[16*128*9];   // packed head conv1 weights
__device__ float g_hb1[16];         // packed head conv1 bias
__device__ float g_h1raw[16*PIX];   // head conv1 partial sums (atomic)
__device__ float g_h1act[16*PIX];   // gelu(head conv1)
__device__ float g_feat1[128*PIX];  // fl1 output [c][p]
__device__ float g_featT[PIX*64];   // fl2 output TRANSPOSED [p][64]
__device__ float4 g_parA[PIX];      // (u, v, A, B)
__device__ float4 g_parB[PIX];      // (C, opa, rx, ry)
__device__ unsigned g_zkey[PIX];
__device__ unsigned g_order[PIX];
__device__ float g_us[PIX], g_vs[PIX], g_As[PIX], g_Bs[PIX], g_Cs[PIX], g_os[PIX];
__device__ float g_rxs[PIX], g_rys[PIX];
__device__ int   g_porig[PIX];      // sorted -> original pixel id
__device__ float g_lev[64*PIX];     // rasterized level [c][p]
__device__ int   g_tlist[NTILE*PIX];  // per tile: 8 segments of 960
__device__ int   g_scnt[NTILE*8];
// winograd buffers (fl1 only this round)
__device__ float g_U1[16*128*128];  // [t][k=128][co=128]
__device__ float g_V[16*128*NT];    // [t][k][n]
__device__ float g_M[16*128*NT];    // [t][co][n]

// ---------------- helpers ----------------
template<int A>
__device__ __forceinline__ float actf(float v){
    if (A == 1) { // ELU
        return v > 0.f ? v : expm1f(v);
    }
    if (A == 2) { // GELU (tanh approx)
        float v3 = v*v*v;
        return 0.5f*v*(1.f + tanhf(0.7978845608028654f*(v + 0.044715f*v3)));
    }
    return v;
}

__device__ __forceinline__ int refl(int c, int n){
    return c < 0 ? -c : (c >= n ? 2*n - 2 - c : c);
}

// ================== direct tiled 3x3 conv (R7, proven) ==================
// PADM: 0=reflect, 1=edge.  ACT: 0=raw atomic partial, 1=ELU, 2=GELU.
// CSPLIT: cin split across gridDim.z (atomic partials).
// OUTT: 1 = write transposed [p][64] layout (requires 64 total out channels).
template<int CIN, int PADM, int ACT, int CSPLIT, int OUTT>
__global__ __launch_bounds__(128)
void conv3x3_t(const float* __restrict__ in, const float* __restrict__ wgt,
               const float* __restrict__ bias, float* __restrict__ out)
{
    __shared__ float s_in[8*10*37];
    __shared__ float s_w[16*72];

    const int tid = threadIdx.x;
    const int tco = tid >> 6;
    const int r   = tid & 63;
    const int ty  = r >> 3;
    const int tx  = r & 7;
    const int x0  = blockIdx.x * 32;
    const int y0  = blockIdx.y * 8;
    const int ncog = gridDim.z / CSPLIT;
    const int cog  = blockIdx.z % ncog;
    const int csp  = blockIdx.z / ncog;
    const int cin0 = csp * (CIN / CSPLIT);
    const int coB  = cog * 16;

    int soffp[3], doffp[3];
    #pragma unroll
    for (int j = 0; j < 3; j++) {
        int e = tid + 128*j;
        if (e < 340) {
            int rr = e / 34, cc = e - rr * 34;
            int yi = y0 - 1 + rr, xi = x0 - 1 + cc;
            if (PADM == 0) { yi = refl(yi, HH); xi = refl(xi, WW); }
            else { yi = yi < 0 ? 0 : (yi >= HH ? HH-1 : yi);
                   xi = xi < 0 ? 0 : (xi >= WW ? WW-1 : xi); }
            soffp[j] = yi*WW + xi;
            doffp[j] = rr*37 + cc;
        }
    }
    int woffp[3];
    #pragma unroll
    for (int j = 0; j < 3; j++) {
        int e = tid + 128*j;
        if (e < 288) {
            int co = e / 18, rem = e - co * 18;
            woffp[j] = (coB + co)*(CIN*9) + rem*4;
        }
    }

    float acc[8][4];
    #pragma unroll
    for (int a = 0; a < 8; a++)
        #pragma unroll
        for (int b = 0; b < 4; b++) acc[a][b] = 0.f;

    const int CHUNKS = CIN / CSPLIT / 8;
    for (int ch = 0; ch < CHUNKS; ch++) {
        const int cb = cin0 + ch * 8;
        __syncthreads();
        const float* inb = in + (size_t)cb * PIX;
        #pragma unroll
        for (int ci = 0; ci < 8; ci++) {
            #pragma unroll
            for (int j = 0; j < 3; j++) {
                int e = tid + 128*j;
                if (e < 340)
                    s_in[ci*370 + doffp[j]] = inb[(size_t)ci*PIX + soffp[j]];
            }
        }
        const float* wb = wgt + cb*9;
        #pragma unroll
        for (int j = 0; j < 3; j++) {
            int e = tid + 128*j;
            if (e < 288)
                *reinterpret_cast<float4*>(&s_w[e*4]) =
                    *reinterpret_cast<const float4*>(&wb[woffp[j]]);
        }
        __syncthreads();

        #pragma unroll
        for (int ci = 0; ci < 8; ci++) {
            float xv[3][6];
            #pragma unroll
            for (int kh = 0; kh < 3; kh++)
                #pragma unroll
                for (int c2 = 0; c2 < 6; c2++)
                    xv[kh][c2] = s_in[ci*370 + (ty+kh)*37 + tx*4 + c2];
            #pragma unroll
            for (int kh = 0; kh < 3; kh++)
                #pragma unroll
                for (int kw = 0; kw < 3; kw++) {
                    #pragma unroll
                    for (int co = 0; co < 8; co++) {
                        float wv = s_w[(tco*8+co)*72 + ci*9 + kh*3 + kw];
                        #pragma unroll
                        for (int px = 0; px < 4; px++)
                            acc[co][px] = fmaf(xv[kh][kw+px], wv, acc[co][px]);
                    }
                }
        }
    }

    const int x = x0 + tx*4, y = y0 + ty;
    if (CSPLIT > 1) {
        #pragma unroll
        for (int co = 0; co < 8; co++) {
            const int cg = coB + tco*8 + co;
            float* op = out + (size_t)cg*PIX + y*WW + x;
            #pragma unroll
            for (int px = 0; px < 4; px++) atomicAdd(op + px, acc[co][px]);
        }
    } else if (OUTT) {
        float bs[8];
        #pragma unroll
        for (int co = 0; co < 8; co++) bs[co] = bias[coB + tco*8 + co];
        #pragma unroll
        for (int px = 0; px < 4; px++) {
            int p = y*WW + x + px;
            float* op = out + (size_t)p*64 + coB + tco*8;
            float4 v0, v1;
            v0.x = actf<ACT>(acc[0][px] + bs[0]);
            v0.y = actf<ACT>(acc[1][px] + bs[1]);
            v0.z = actf<ACT>(acc[2][px] + bs[2]);
            v0.w = actf<ACT>(acc[3][px] + bs[3]);
            v1.x = actf<ACT>(acc[4][px] + bs[4]);
            v1.y = actf<ACT>(acc[5][px] + bs[5]);
            v1.z = actf<ACT>(acc[6][px] + bs[6]);
            v1.w = actf<ACT>(acc[7][px] + bs[7]);
            reinterpret_cast<float4*>(op)[0] = v0;
            reinterpret_cast<float4*>(op)[1] = v1;
        }
    } else {
        #pragma unroll
        for (int co = 0; co < 8; co++) {
            const int cg = coB + tco*8 + co;
            float* op = out + (size_t)cg*PIX + y*WW + x;
            const float b = bias[cg];
            float4 vv;
            vv.x = actf<ACT>(acc[co][0] + b);
            vv.y = actf<ACT>(acc[co][1] + b);
            vv.z = actf<ACT>(acc[co][2] + b);
            vv.w = actf<ACT>(acc[co][3] + b);
            *reinterpret_cast<float4*>(op) = vv;
        }
    }
}

// ================== Winograd F(2x2,3x3) — fl1 only this round ==================
__device__ __forceinline__ void wtrans9(const float* g9, float* u16)
{
    float t[4][3];
    #pragma unroll
    for (int j = 0; j < 3; j++) {
        float g0 = g9[0*3+j], g1 = g9[1*3+j], g2 = g9[2*3+j];
        t[0][j] = g0;
        t[1][j] = 0.5f*(g0 + g1 + g2);
        t[2][j] = 0.5f*(g0 - g1 + g2);
        t[3][j] = g2;
    }
    #pragma unroll
    for (int i = 0; i < 4; i++) {
        float a = t[i][0], b = t[i][1], c = t[i][2];
        u16[i*4+0] = a;
        u16[i*4+1] = 0.5f*(a + b + c);
        u16[i*4+2] = 0.5f*(a - b + c);
        u16[i*4+3] = c;
    }
}

__global__ void wtrans1_kernel(const float* __restrict__ w1)
{
    int idx = blockIdx.x * 256 + threadIdx.x;
    if (idx >= 16384) return;                 // 128co x 128ci
    int co = idx & 127, ci = idx >> 7;
    float u[16];
    wtrans9(w1 + (size_t)(co*128 + ci)*9, u);
    #pragma unroll
    for (int t = 0; t < 16; t++) g_U1[(t*128 + ci)*128 + co] = u[t];
}

// input transform: V = B^T d B, reflect padding inline. src layout [c][p].
__global__ void vtrans_kernel(const float* __restrict__ src)
{
    int idx = blockIdx.x * 256 + threadIdx.x;
    if (idx >= 128 * NT) return;
    int ci = idx / NT, tile = idx - ci * NT;
    int ty = tile / 80, tx = tile - ty * 80;

    int ry[4], rx[4];
    #pragma unroll
    for (int r = 0; r < 4; r++) { ry[r] = refl(2*ty - 1 + r, HH); rx[r] = refl(2*tx - 1 + r, WW); }

    const float* s = src + (size_t)ci * PIX;
    float d[4][4];
    #pragma unroll
    for (int r = 0; r < 4; r++)
        #pragma unroll
        for (int c = 0; c < 4; c++)
            d[r][c] = s[ry[r]*WW + rx[c]];

    float t[4][4];
    #pragma unroll
    for (int c = 0; c < 4; c++) {
        t[0][c] = d[0][c] - d[2][c];
        t[1][c] = d[1][c] + d[2][c];
        t[2][c] = d[2][c] - d[1][c];
        t[3][c] = d[1][c] - d[3][c];
    }
    float v[4][4];
    #pragma unroll
    for (int r = 0; r < 4; r++) {
        v[r][0] = t[r][0] - t[r][2];
        v[r][1] = t[r][1] + t[r][2];
        v[r][2] = t[r][2] - t[r][1];
        v[r][3] = t[r][1] - t[r][3];
    }
    #pragma unroll
    for (int r = 0; r < 4; r++)
        #pragma unroll
        for (int c = 0; c < 4; c++)
            g_V[((r*4 + c)*128 + ci)*NT + tile] = v[r][c];
}

// batched GEMM: M[t][co][n] = sum_k U1[t][k][co] * V[t][k][n]
// block: 64co x 32n, 128 threads (each 4co x 4n), k-chunks of 32.
__global__ __launch_bounds__(128)
void wino_gemm1()
{
    __shared__ float sU[32][64];
    __shared__ float sV[32][32];

    const int tid = threadIdx.x;
    const int nB  = blockIdx.x;      // 0..59
    const int coB = blockIdx.y;      // 0..1
    const int t   = blockIdx.z;      // 0..15
    const int coq = tid >> 3;        // 0..15
    const int nq  = tid & 7;         // 0..7

    const float* Ut = g_U1 + (size_t)t * 128 * 128;
    const float* Vt = g_V  + (size_t)t * 128 * NT;

    float acc[4][4];
    #pragma unroll
    for (int i = 0; i < 4; i++)
        #pragma unroll
        for (int j = 0; j < 4; j++) acc[i][j] = 0.f;

    for (int k0 = 0; k0 < 128; k0 += 32) {
        __syncthreads();
        #pragma unroll
        for (int j = 0; j < 4; j++) {
            int e = tid + 128*j;           // 512 float4 slots
            int kk = e >> 4, cq = e & 15;
            *reinterpret_cast<float4*>(&sU[kk][cq*4]) =
                *reinterpret_cast<const float4*>(&Ut[(size_t)(k0+kk)*128 + coB*64 + cq*4]);
        }
        #pragma unroll
        for (int j = 0; j < 2; j++) {
            int e = tid + 128*j;           // 256 float4 slots
            int kk = e >> 3, cq = e & 7;
            *reinterpret_cast<float4*>(&sV[kk][cq*4]) =
                *reinterpret_cast<const float4*>(&Vt[(size_t)(k0+kk)*NT + nB*32 + cq*4]);
        }
        __syncthreads();

        #pragma unroll
        for (int kk = 0; kk < 32; kk++) {
            float4 a = *reinterpret_cast<const float4*>(&sU[kk][coq*4]);
            float4 b = *reinterpret_cast<const float4*>(&sV[kk][nq*4]);
            acc[0][0] = fmaf(a.x, b.x, acc[0][0]); acc[0][1] = fmaf(a.x, b.y, acc[0][1]);
            acc[0][2] = fmaf(a.x, b.z, acc[0][2]); acc[0][3] = fmaf(a.x, b.w, acc[0][3]);
            acc[1][0] = fmaf(a.y, b.x, acc[1][0]); acc[1][1] = fmaf(a.y, b.y, acc[1][1]);
            acc[1][2] = fmaf(a.y, b.z, acc[1][2]); acc[1][3] = fmaf(a.y, b.w, acc[1][3]);
            acc[2][0] = fmaf(a.z, b.x, acc[2][0]); acc[2][1] = fmaf(a.z, b.y, acc[2][1]);
            acc[2][2] = fmaf(a.z, b.z, acc[2][2]); acc[2][3] = fmaf(a.z, b.w, acc[2][3]);
            acc[3][0] = fmaf(a.w, b.x, acc[3][0]); acc[3][1] = fmaf(a.w, b.y, acc[3][1]);
            acc[3][2] = fmaf(a.w, b.z, acc[3][2]); acc[3][3] = fmaf(a.w, b.w, acc[3][3]);
        }
    }

    #pragma unroll
    for (int i = 0; i < 4; i++) {
        int co = coB*64 + coq*4 + i;
        float4 vv = make_float4(acc[i][0], acc[i][1], acc[i][2], acc[i][3]);
        *reinterpret_cast<float4*>(&g_M[((size_t)t*128 + co)*NT + nB*32 + nq*4]) = vv;
    }
}

// output transform: Y = A^T M A + bias, ELU, writes [c][p].
__global__ void otrans1_kernel(const float* __restrict__ bias, float* __restrict__ dst)
{
    int idx = blockIdx.x * 256 + threadIdx.x;
    if (idx >= 128 * NT) return;
    int co = idx / NT, tile = idx - co * NT;
    int ty = tile / 80, tx = tile - ty * 80;

    float m[4][4];
    #pragma unroll
    for (int r = 0; r < 4; r++)
        #pragma unroll
        for (int c = 0; c < 4; c++)
            m[r][c] = g_M[((size_t)(r*4 + c)*128 + co)*NT + tile];

    float s0[4], s1[4];
    #pragma unroll
    for (int c = 0; c < 4; c++) {
        s0[c] = m[0][c] + m[1][c] + m[2][c];
        s1[c] = m[1][c] - m[2][c] - m[3][c];
    }
    const float b = bias[co];
    float y00 = actf<1>(s0[0] + s0[1] + s0[2] + b);
    float y01 = actf<1>(s0[1] - s0[2] - s0[3] + b);
    float y10 = actf<1>(s1[0] + s1[1] + s1[2] + b);
    float y11 = actf<1>(s1[1] - s1[2] - s1[3] + b);

    int py = 2*ty, px = 2*tx;
    float* o = dst + (size_t)co*PIX + py*WW + px;
    o[0] = y00; o[1] = y01;
    o[WW] = y10; o[WW+1] = y11;
}

// ---------------- prep: pack head conv1 weights + zero partial buffer ----------------
__global__ void prep_kernel(const float* __restrict__ rw1, const float* __restrict__ sw1,
                            const float* __restrict__ ow1, const float* __restrict__ rb1,
                            const float* __restrict__ sb1, const float* __restrict__ ob1)
{
    int i = blockIdx.x * 256 + threadIdx.x;
    if (i < 16*1152) {
        int co = i / 1152, rem = i - co*1152;
        float v;
        if (co < 8)       v = rw1[co*1152 + rem];
        else if (co < 14) v = sw1[(co-8)*1152 + rem];
        else              v = ow1[(co-14)*1152 + rem];
        g_hw1[i] = v;
    }
    if (i < 16) {
        float b;
        if (i < 8)       b = rb1[i];
        else if (i < 14) b = sb1[i-8];
        else             b = ob1[i-14];
        g_hb1[i] = b;
    }
    if (i < 16*PIX) g_h1raw[i] = 0.f;
}

__global__ void h1_epilogue_kernel()
{
    int i = blockIdx.x * 256 + threadIdx.x;
    if (i < 16*PIX) {
        int c = i / PIX;
        float v = g_h1raw[i] + g_hb1[c];
        float v3 = v*v*v;
        g_h1act[i] = 0.5f*v*(1.f + tanhf(0.7978845608028654f*(v + 0.044715f*v3)));
    }
}

// ---------------- head conv2 + gaussian precompute ----------------
__global__ void heads2_kernel(const float* __restrict__ disp,
                              const float* __restrict__ invK, const float* __restrict__ Kmat,
                              const float* __restrict__ rw2, const float* __restrict__ rb2,
                              const float* __restrict__ sw2, const float* __restrict__ sb2,
                              const float* __restrict__ ow2, const float* __restrict__ ob2)
{
    int p = blockIdx.x * 256 + threadIdx.x;
    if (p >= PIX) return;
    int yy = p / WW, xx = p - yy*WW;

    int nb[9];
    #pragma unroll
    for (int kh = 0; kh < 3; kh++) {
        int yi = yy - 1 + kh; yi = yi < 0 ? 0 : (yi >= HH ? HH-1 : yi);  // edge pad
        #pragma unroll
        for (int kw = 0; kw < 3; kw++) {
            int xi = xx - 1 + kw; xi = xi < 0 ? 0 : (xi >= WW ? WW-1 : xi);
            nb[kh*3+kw] = yi*WW + xi;
        }
    }

    float q[4] = { rb2[0], rb2[1], rb2[2], rb2[3] };
    for (int ci = 0; ci < 8; ci++) {
        #pragma unroll
        for (int t = 0; t < 9; t++) {
            float a = g_h1act[ci*PIX + nb[t]];
            #pragma unroll
            for (int k = 0; k < 4; k++) q[k] = fmaf(a, rw2[k*72 + ci*9 + t], q[k]);
        }
    }
    float nrm = sqrtf(q[0]*q[0] + q[1]*q[1] + q[2]*q[2] + q[3]*q[3]);
    nrm = fmaxf(nrm, 1e-12f);
    float inr = 1.f / nrm;
    float qw = q[0]*inr, qx = q[1]*inr, qy = q[2]*inr, qz = q[3]*inr;

    float s3[3] = { sb2[0], sb2[1], sb2[2] };
    for (int ci = 0; ci < 6; ci++) {
        #pragma unroll
        for (int t = 0; t < 9; t++) {
            float a = g_h1act[(8+ci)*PIX + nb[t]];
            #pragma unroll
            for (int k = 0; k < 3; k++) s3[k] = fmaf(a, sw2[k*54 + ci*9 + t], s3[k]);
        }
    }
    float s0 = fabsf(s3[0]), s1 = fabsf(s3[1]), s2 = fabsf(s3[2]);

    float ov = ob2[0];
    for (int ci = 0; ci < 2; ci++) {
        #pragma unroll
        for (int t = 0; t < 9; t++)
            ov = fmaf(g_h1act[(14+ci)*PIX + nb[t]], ow2[ci*9 + t], ov);
    }
    float opa = 1.f / (1.f + expf(-ov));

    float dsp = disp[p];
    float scaled = (1.f/100.f) + (1.f/0.1f - 1.f/100.f) * dsp;
    float d = 1.f / scaled;
    d = fminf(fmaxf(d, 0.1f), 100.f);
    float fxp = (float)xx, fyp = (float)yy;
    float X = (invK[0]*fxp + invK[1]*fyp + invK[2])  * d;
    float Y = (invK[4]*fxp + invK[5]*fyp + invK[6])  * d;
    float Z = (invK[8]*fxp + invK[9]*fyp + invK[10]) * d;

    float fx = Kmat[0], fy = Kmat[5], cx = Kmat[2], cy = Kmat[6];

    float r00 = 1.f - 2.f*(qy*qy + qz*qz), r01 = 2.f*(qx*qy - qw*qz), r02 = 2.f*(qx*qz + qw*qy);
    float r10 = 2.f*(qx*qy + qw*qz), r11 = 1.f - 2.f*(qx*qx + qz*qz), r12 = 2.f*(qy*qz - qw*qx);
    float r20 = 2.f*(qx*qz - qw*qy), r21 = 2.f*(qy*qz + qw*qx), r22 = 1.f - 2.f*(qx*qx + qy*qy);
    float m00 = r00*s0, m01 = r01*s1, m02 = r02*s2;
    float m10 = r10*s0, m11 = r11*s1, m12 = r12*s2;
    float m20 = r20*s0, m21 = r21*s1, m22 = r22*s2;
    float S00 = m00*m00 + m01*m01 + m02*m02;
    float S01 = m00*m10 + m01*m11 + m02*m12;
    float S02 = m00*m20 + m01*m21 + m02*m22;
    float S11 = m10*m10 + m11*m11 + m12*m12;
    float S12 = m10*m20 + m11*m21 + m12*m22;
    float S22 = m20*m20 + m21*m21 + m22*m22;

    float iz = 1.f / Z;
    float j00 = fx*iz,  j02 = -fx*X*iz*iz;
    float j11 = fy*iz,  j12 = -fy*Y*iz*iz;
    float t00 = j00*S00 + j02*S02;
    float t01 = j00*S01 + j02*S12;
    float t02 = j00*S02 + j02*S22;
    float cov00 = t00*j00 + t02*j02;
    float cov01 = t01*j11 + t02*j12;
    float t11 = j11*S11 + j12*S12;
    float t12 = j11*S12 + j12*S22;
    float cov11 = t11*j11 + t12*j12;

    float a = cov00 + 0.3f, b = cov01, c = cov11 + 0.3f;
    float det = a*c - b*b;
    float idet = 1.f / det;

    float A = c * idet, Bq = -b * idet, C = a * idet;
    g_parA[p] = make_float4(fx*X*iz + cx, fy*Y*iz + cy, A, Bq);
    g_parB[p] = make_float4(C, opa, sqrtf(40.f*a), sqrtf(40.f*c));
    g_zkey[p] = __float_as_uint(Z);
}

// ---------------- bitonic sort ----------------
__global__ __launch_bounds__(1024) void sort_kernel()
{
    __shared__ unsigned skey[NPAD];
    __shared__ unsigned short sidx[NPAD];
    const int tid = threadIdx.x;
    for (int i = tid; i < NPAD; i += 1024) {
        skey[i] = (i < PIX) ? g_zkey[i] : 0xFFFFFFFFu;
        sidx[i] = (unsigned short)i;
    }
    __syncthreads();
    for (int k = 2; k <= NPAD; k <<= 1) {
        for (int j = k >> 1; j > 0; j >>= 1) {
            for (int i = tid; i < NPAD; i += 1024) {
                int ixj = i ^ j;
                if (ixj > i) {
                    bool up = ((i & k) == 0);
                    unsigned a = skey[i], b = skey[ixj];
                    unsigned short ia = sidx[i], ib = sidx[ixj];
                    bool gt = (a > b) || (a == b && ia > ib);
                    if (gt == up) {
                        skey[i] = b; skey[ixj] = a;
                        sidx[i] = ib; sidx[ixj] = ia;
                    }
                }
            }
            __syncthreads();
        }
    }
    for (int i = tid; i < PIX; i += 1024) g_order[i] = sidx[i];
}

// ---------------- gather params into sorted SoA ----------------
__global__ void gatherP_kernel()
{
    int n = blockIdx.x * 256 + threadIdx.x;
    if (n >= PIX) return;
    unsigned p = g_order[n];
    float4 a = g_parA[p], b = g_parB[p];
    g_us[n] = a.x;  g_vs[n] = a.y;  g_As[n] = a.z;  g_Bs[n] = a.w;
    g_Cs[n] = b.x;  g_os[n] = b.y;  g_rxs[n] = b.z; g_rys[n] = b.w;
    g_porig[n] = (int)p;
}

// -------- tile binning: 8 warps per tile, depth-ordered segments of 960 (R7) --------
__global__ __launch_bounds__(256) void bin_kernel()
{
    const int tile = blockIdx.x;
    const int lane = threadIdx.x & 31;
    const int w    = threadIdx.x >> 5;
    const float x0 = (float)((tile % 10) * 16);
    const float y0 = (float)((tile / 10) * 16);
    const float x1 = x0 + 15.f, y1 = y0 + 15.f;
    int* list = g_tlist + tile * PIX + w * 960;
    int cnt = 0;
    for (int b = 0; b < 960; b += 32) {
        int n = w*960 + b + lane;
        float u = g_us[n], v = g_vs[n], rx = g_rxs[n], ry = g_rys[n];
        bool hit = (u - rx <= x1) && (u + rx >= x0) && (v - ry <= y1) && (v + ry >= y0);
        unsigned m = __ballot_sync(0xffffffffu, hit);
        if (hit) list[cnt + __popc(m & ((1u << lane) - 1u))] = n;
        cnt += __popc(m);
    }
    if (lane == 0) g_scnt[tile*8 + w] = cnt;
}

// ---- rasterize: thread per pixel (16x16 tile, R7), 16 channels per block ----
__global__ __launch_bounds__(256) void raster_kernel()
{
    __shared__ int   sp[64];
    __shared__ float su[64], sv[64], sA[64], sB[64], sC[64], so[64];
    __shared__ float sf[64*16];

    const int tile = blockIdx.x;
    const int q    = blockIdx.y;       // channel quarter
    const int tid  = threadIdx.x;
    const int px = (tile % 10) * 16 + (tid & 15);
    const int py = (tile / 10) * 16 + (tid >> 4);
    const float gx = (float)px, gy = (float)py;

    float acc[16];
    #pragma unroll
    for (int c = 0; c < 16; c++) acc[c] = 0.f;
    float T = 1.f;
    bool done = false;
    bool alldone = false;

    for (int seg = 0; seg < 8 && !alldone; seg++) {
        const int cnt = g_scnt[tile*8 + seg];
        const int* list = g_tlist + tile * PIX + seg * 960;

        for (int base = 0; base < cnt; base += 64) {
            const int m = min(64, cnt - base);
            __syncthreads();
            if (tid < m) {
                int n = list[base + tid];
                sp[tid] = g_porig[n];
                su[tid] = g_us[n]; sv[tid] = g_vs[n];
                sA[tid] = g_As[n]; sB[tid] = g_Bs[n];
                sC[tid] = g_Cs[n]; so[tid] = g_os[n];
            }
            __syncthreads();
            for (int e = tid; e < m * 16; e += 256) {
                int g = e >> 4, c = e & 15;
                sf[e] = g_featT[(size_t)sp[g]*64 + q*16 + c];
            }
            __syncthreads();

            if (!done) {
                for (int g = 0; g < m; g++) {
                    float dx = gx - su[g], dy = gy - sv[g];
                    float pw = -0.5f*(sA[g]*dx*dx + sC[g]*dy*dy) - sB[g]*dx*dy;
                    if (pw <= 0.f && pw > -20.f) {
                        float alpha = fminf(so[g]*__expf(pw), 0.99f);
                        float wv = alpha * T;
                        T -= wv;
                        if (wv > 1e-9f) {
                            const float4* fp = reinterpret_cast<const float4*>(sf + g*16);
                            #pragma unroll
                            for (int c4 = 0; c4 < 4; c4++) {
                                float4 f = fp[c4];
                                acc[c4*4+0] = fmaf(wv, f.x, acc[c4*4+0]);
                                acc[c4*4+1] = fmaf(wv, f.y, acc[c4*4+1]);
                                acc[c4*4+2] = fmaf(wv, f.z, acc[c4*4+2]);
                                acc[c4*4+3] = fmaf(wv, f.w, acc[c4*4+3]);
                            }
                        }
                        if (T < 1e-7f) { done = true; }
                    }
                }
            }
            if (__syncthreads_and(done)) { alldone = true; break; }
        }
    }

    const int p = py * WW + px;
    #pragma unroll
    for (int c = 0; c < 16; c++)
        g_lev[(size_t)(q*16 + c)*PIX + p] = acc[c];
}

// ---------------- launch ----------------
extern "C" void kernel_launch(void* const* d_in, const int* in_sizes, int n_in,
                              void* d_out, int out_size)
{
    const float* init_feature = (const float*)d_in[0];
    const float* disp   = (const float*)d_in[1];
    const float* invK   = (const float*)d_in[2];
    const float* Kmat   = (const float*)d_in[3];
    const float* rot_w1 = (const float*)d_in[4];
    const float* rot_b1 = (const float*)d_in[5];
    const float* rot_w2 = (const float*)d_in[6];
    const float* rot_b2 = (const float*)d_in[7];
    const float* scl_w1 = (const float*)d_in[8];
    const float* scl_b1 = (const float*)d_in[9];
    const float* scl_w2 = (const float*)d_in[10];
    const float* scl_b2 = (const float*)d_in[11];
    const float* opa_w1 = (const float*)d_in[12];
    const float* opa_b1 = (const float*)d_in[13];
    const float* opa_w2 = (const float*)d_in[14];
    const float* opa_b2 = (const float*)d_in[15];
    const float* fl_w1  = (const float*)d_in[16];
    const float* fl_b1  = (const float*)d_in[17];
    const float* fl_w2  = (const float*)d_in[18];
    const float* fl_b2  = (const float*)d_in[19];
    const float* fr_w   = (const float*)d_in[20];
    const float* fr_b   = (const float*)d_in[21];
    float* out = (float*)d_out;

    float *p_hw1, *p_h1raw, *p_feat1, *p_featT, *p_lev;
    cudaGetSymbolAddress((void**)&p_hw1,    g_hw1);
    cudaGetSymbolAddress((void**)&p_h1raw,  g_h1raw);
    cudaGetSymbolAddress((void**)&p_feat1,  g_feat1);
    cudaGetSymbolAddress((void**)&p_featT,  g_featT);
    cudaGetSymbolAddress((void**)&p_lev,    g_lev);

    static cudaStream_t s1 = nullptr;
    static cudaEvent_t e0 = nullptr, e1 = nullptr;
    if (!s1) {
        cudaStreamCreateWithFlags(&s1, cudaStreamNonBlocking);
        cudaEventCreateWithFlags(&e0, cudaEventDisableTiming);
        cudaEventCreateWithFlags(&e1, cudaEventDisableTiming);
    }

    // fork: side chain runs concurrently with main conv chain (R7 structure)
    cudaEventRecord(e0, 0);
    cudaStreamWaitEvent(s1, e0, 0);

    // ---- side chain (s1): head conv path -> sort -> param gather -> bin ----
    prep_kernel<<<480, 256, 0, s1>>>(rot_w1, scl_w1, opa_w1, rot_b1, scl_b1, opa_b1);
    conv3x3_t<128, 1, 0, 4, 0><<<dim3(5, 6, 4), 128, 0, s1>>>(init_feature, p_hw1, nullptr, p_h1raw);
    h1_epilogue_kernel<<<480, 256, 0, s1>>>();
    heads2_kernel<<<30, 256, 0, s1>>>(disp, invK, Kmat, rot_w2, rot_b2, scl_w2, scl_b2, opa_w2, opa_b2);
    sort_kernel<<<1, 1024, 0, s1>>>();
    gatherP_kernel<<<30, 256, 0, s1>>>();
    bin_kernel<<<NTILE, 256, 0, s1>>>();
    cudaEventRecord(e1, s1);

    // ---- main chain (stream 0): fl1 via Winograd, fl2 direct ----
    wtrans1_kernel<<<64, 256>>>(fl_w1);
    vtrans_kernel<<<960, 256>>>(init_feature);
    wino_gemm1<<<dim3(60, 2, 16), 128>>>();
    otrans1_kernel<<<960, 256>>>(fl_b1, p_feat1);

    conv3x3_t<128, 0, 1, 1, 1><<<dim3(5, 6, 4), 128>>>(p_feat1, fl_w2, fl_b2, p_featT);

    // join, then rasterize + final conv (direct)
    cudaStreamWaitEvent(0, e1, 0);
    raster_kernel<<<dim3(NTILE, 4), 256>>>();
    conv3x3_t<64, 0, 1, 1, 0><<<dim3(5, 6, 8), 128>>>(p_lev, fr_w, fr_b, out);
}